// round 8
// baseline (speedup 1.0000x reference)
#include <cuda_runtime.h>
#include <cstdint>

// ----------------------------------------------------------------------------
// GIN forward on GB300 (base sm_103 PTX — no tcgen05 available in this build):
// CSR gather aggregation + mma.sync bf16 (3x error-compensated) GEMMs with
// fused bias/relu/BN epilogue, atomic pool, fused head.
// ----------------------------------------------------------------------------

#define NMAX 50048
#define EMAX 800000
#define HDIM 128
#define GMAX 512

__device__ float g_h[(size_t)NMAX * HDIM];
__device__ float g_hpre[(size_t)NMAX * HDIM];
__device__ float g_h1[(size_t)NMAX * HDIM];
__device__ float g_hpre2[NMAX * 2];
__device__ int   g_deg[NMAX];
__device__ int   g_off[NMAX];
__device__ int   g_cnt[NMAX];
__device__ int   g_csr[EMAX];
__device__ float g_pooled[GMAX * HDIM];
// 9 weight mats x (hi plane 16384 + lo plane 16384) bf16, transposed [n][k]
__device__ unsigned short g_wprep[9 * 32768];

// ------------------------------ helpers -------------------------------------

__device__ __forceinline__ uint32_t smem_to_u32(const void* p) {
    uint32_t a;
    asm("{ .reg .u64 t; cvta.to.shared.u64 t, %1; cvt.u32.u64 %0, t; }"
        : "=r"(a) : "l"(p));
    return a;
}

// pack two floats to bf16x2 (rn): result lo-half = lo arg, hi-half = hi arg
__device__ __forceinline__ uint32_t pack_bf16x2(float lo, float hi) {
    uint32_t r;
    asm("cvt.rn.bf16x2.f32 %0, %1, %2;" : "=r"(r) : "f"(hi), "f"(lo));
    return r;
}

__device__ __forceinline__ void ldsm_x4(uint32_t r[4], uint32_t addr) {
    asm volatile("ldmatrix.sync.aligned.m8n8.x4.shared.b16 {%0,%1,%2,%3}, [%4];"
                 : "=r"(r[0]), "=r"(r[1]), "=r"(r[2]), "=r"(r[3]) : "r"(addr));
}

__device__ __forceinline__ void mma_bf16(float c[4], const uint32_t a[4],
                                         const uint32_t b[2]) {
    asm volatile(
        "mma.sync.aligned.m16n8k16.row.col.f32.bf16.bf16.f32 "
        "{%0,%1,%2,%3}, {%4,%5,%6,%7}, {%8,%9}, {%0,%1,%2,%3};"
        : "+f"(c[0]), "+f"(c[1]), "+f"(c[2]), "+f"(c[3])
        : "r"(a[0]), "r"(a[1]), "r"(a[2]), "r"(a[3]), "r"(b[0]), "r"(b[1]));
}

// --------------------------- CSR construction -------------------------------

__global__ void zero_kernel(int n, int gh) {
    int i = blockIdx.x * blockDim.x + threadIdx.x;
    if (i < n) { g_deg[i] = 0; g_cnt[i] = 0; }
    if (i < gh) g_pooled[i] = 0.0f;
}

__global__ void hist_kernel(const int* __restrict__ dst, int e, int n) {
    int i = blockIdx.x * blockDim.x + threadIdx.x;
    if (i < e) {
        int d = dst[i];
        if (d >= 0 && d < n) atomicAdd(&g_deg[d], 1);
    }
}

__global__ void scan_kernel(int n) {
    __shared__ int sums[1024];
    int t = threadIdx.x;
    int chunk = (n + 1023) >> 10;
    int start = t * chunk;
    int end = start + chunk; if (end > n) end = n;
    int s = 0;
    for (int i = start; i < end; i++) s += g_deg[i];
    sums[t] = s;
    __syncthreads();
    for (int d = 1; d < 1024; d <<= 1) {
        int v = (t >= d) ? sums[t - d] : 0;
        __syncthreads();
        sums[t] += v;
        __syncthreads();
    }
    int run = (t == 0) ? 0 : sums[t - 1];
    for (int i = start; i < end; i++) { g_off[i] = run; run += g_deg[i]; }
}

__global__ void fill_kernel(const int* __restrict__ src,
                            const int* __restrict__ dst, int e, int n) {
    int i = blockIdx.x * blockDim.x + threadIdx.x;
    if (i < e) {
        int d = dst[i];
        int s = src[i];
        if (d >= 0 && d < n && s >= 0 && s < n) {
            int p = g_off[d] + atomicAdd(&g_cnt[d], 1);
            g_csr[p] = s;
        }
    }
}

// ----------------------- Weight prep (bf16 hi/lo, [n][k]) -------------------

__global__ void wprep_kernel(const float* __restrict__ src, int slot0, int nmat) {
    int i = blockIdx.x * blockDim.x + threadIdx.x;
    int total = nmat * 16384;
    if (i >= total) return;
    int m = i / 16384;
    int r = i - m * 16384;
    int k = r >> 7;           // 0..127
    int nn = r & 127;         // 0..127
    float v = src[i];         // src[m][k][nn]
    uint32_t ph = pack_bf16x2(v, v);
    uint16_t hb = (uint16_t)(ph & 0xFFFFu);
    float hf = __uint_as_float((uint32_t)hb << 16);
    uint32_t pl = pack_bf16x2(v - hf, v - hf);
    uint16_t lb = (uint16_t)(pl & 0xFFFFu);
    int base = (slot0 + m) * 32768;
    g_wprep[base + nn * 128 + k] = hb;           // hi plane, transposed [n][k]
    g_wprep[base + 16384 + nn * 128 + k] = lb;   // lo plane
}

// --------------------------- Layer 0 (d_in = 2) -----------------------------

__global__ void agg2_kernel(const float* __restrict__ x, int n) {
    int i = blockIdx.x * blockDim.x + threadIdx.x;
    if (i >= n) return;
    float a0 = x[i * 2], a1 = x[i * 2 + 1];
    int o = g_off[i], d = g_deg[i];
    for (int e = 0; e < d; e++) {
        int s = g_csr[o + e];
        a0 += x[s * 2];
        a1 += x[s * 2 + 1];
    }
    g_hpre2[i * 2] = a0;
    g_hpre2[i * 2 + 1] = a1;
}

__global__ void mlp0_kernel(const float* __restrict__ W1,
                            const float* __restrict__ b1, int n) {
    int t = blockIdx.x * blockDim.x + threadIdx.x;
    int node = t >> 5, seg = t & 31;
    if (node >= n) return;
    int c = seg * 4;
    float h0 = g_hpre2[node * 2];
    float h1v = g_hpre2[node * 2 + 1];
    float4 w0 = *(const float4*)&W1[c];
    float4 w1 = *(const float4*)&W1[HDIM + c];
    float4 bb = *(const float4*)&b1[c];
    float4 v;
    v.x = fmaxf(fmaf(h0, w0.x, fmaf(h1v, w1.x, bb.x)), 0.0f);
    v.y = fmaxf(fmaf(h0, w0.y, fmaf(h1v, w1.y, bb.y)), 0.0f);
    v.z = fmaxf(fmaf(h0, w0.z, fmaf(h1v, w1.z, bb.z)), 0.0f);
    v.w = fmaxf(fmaf(h0, w0.w, fmaf(h1v, w1.w, bb.w)), 0.0f);
    *(float4*)&g_h1[(size_t)node * HDIM + c] = v;
}

// --------------------- Aggregation for 128-dim layers -----------------------

__global__ void agg_kernel(int n) {
    int gt = blockIdx.x * blockDim.x + threadIdx.x;
    int node = gt >> 5, lane = gt & 31;
    if (node >= n) return;
    const float4* hp = (const float4*)g_h;
    float4 acc = hp[(size_t)node * 32 + lane];
    int o = g_off[node], d = g_deg[node];
    int e = 0;
    int d4 = d & ~3;
    for (; e < d4; e += 4) {
        int s0 = g_csr[o + e];
        int s1 = g_csr[o + e + 1];
        int s2 = g_csr[o + e + 2];
        int s3 = g_csr[o + e + 3];
        float4 v0 = hp[(size_t)s0 * 32 + lane];
        float4 v1 = hp[(size_t)s1 * 32 + lane];
        float4 v2 = hp[(size_t)s2 * 32 + lane];
        float4 v3 = hp[(size_t)s3 * 32 + lane];
        acc.x += v0.x + v1.x + v2.x + v3.x;
        acc.y += v0.y + v1.y + v2.y + v3.y;
        acc.z += v0.z + v1.z + v2.z + v3.z;
        acc.w += v0.w + v1.w + v2.w + v3.w;
    }
    for (; e < d; e++) {
        int s = g_csr[o + e];
        float4 v = hp[(size_t)s * 32 + lane];
        acc.x += v.x; acc.y += v.y; acc.z += v.z; acc.w += v.w;
    }
    ((float4*)g_hpre)[(size_t)node * 32 + lane] = acc;
}

// ---------------- Tensor-core GEMM: C = post(A[n,128] @ W[128,128]) ---------
// mma.sync m16n8k16 bf16, 3-term compensation (hi*hi + hi*lo + lo*hi).
// smem layout (bytes):
//   0      bias[128] f32
//   512    sc[128]
//   1024   sh[128]
//   2048   A_hi  128 rows x 272B (128 bf16 + 8 pad)
//   36864  A_lo
//   71680  W_hi  (Wt[n][k] bf16, padded rows)
//   106496 W_lo
#define PITCH 272
#define A_HI 2048
#define A_LO 36864
#define W_HI 71680
#define W_LO 106496
#define GEMM_SMEM_BYTES 141312

__global__ void __launch_bounds__(256)
gemm_tc(const float* __restrict__ A, const unsigned short* __restrict__ Wp,
        const float* __restrict__ bias,
        const float* __restrict__ gamma, const float* __restrict__ beta,
        const float* __restrict__ mean, const float* __restrict__ var,
        float* __restrict__ C, int n) {
    extern __shared__ __align__(16) char smem[];
    uint32_t sb = smem_to_u32(smem);
    int tid = threadIdx.x;
    int wid = tid >> 5;
    int lane = tid & 31;
    int row0 = blockIdx.x * 128;

    float* sm_bias = (float*)(smem + 0);
    float* sm_sc   = (float*)(smem + 512);
    float* sm_sh   = (float*)(smem + 1024);
    if (tid < 128) {
        float b = bias[tid];
        float scv = 1.0f, shv = 0.0f;
        if (gamma != nullptr) {
            scv = gamma[tid] * rsqrtf(var[tid] + 1e-5f);
            shv = beta[tid] - mean[tid] * scv;
        }
        sm_bias[tid] = b; sm_sc[tid] = scv; sm_sh[tid] = shv;
    }

    // W copy: 2 planes x 2048 uint4
#pragma unroll
    for (int it = 0; it < 16; it++) {
        int u = it * 256 + tid;             // 0..4095
        int plane = u >> 11;                // 0 hi, 1 lo
        int idx = u & 2047;
        int nn = idx >> 4, cu = idx & 15;   // row, 16B unit
        uint4 v = ((const uint4*)Wp)[u];
        char* dstb = smem + (plane ? W_LO : W_HI) + nn * PITCH + cu * 16;
        *(uint4*)dstb = v;
    }

    // A load + bf16 hi/lo split: 128 rows x 32 float4
#pragma unroll
    for (int it = 0; it < 16; it++) {
        int idx = it * 256 + tid;           // float4 index
        int row = idx >> 5, c4 = idx & 31;
        int gr = row0 + row;
        float4 v = make_float4(0.f, 0.f, 0.f, 0.f);
        if (gr < n) v = *(const float4*)&A[(size_t)gr * 128 + c4 * 4];
        uint32_t h01 = pack_bf16x2(v.x, v.y);
        uint32_t h23 = pack_bf16x2(v.z, v.w);
        float hx = __uint_as_float(h01 << 16);
        float hy = __uint_as_float(h01 & 0xFFFF0000u);
        float hz = __uint_as_float(h23 << 16);
        float hw = __uint_as_float(h23 & 0xFFFF0000u);
        uint32_t l01 = pack_bf16x2(v.x - hx, v.y - hy);
        uint32_t l23 = pack_bf16x2(v.z - hz, v.w - hw);
        *(uint2*)(smem + A_HI + row * PITCH + c4 * 8) = make_uint2(h01, h23);
        *(uint2*)(smem + A_LO + row * PITCH + c4 * 8) = make_uint2(l01, l23);
    }
    __syncthreads();

    // warp tile: rows m0..m0+31, cols n0..n0+63
    int m0 = (wid & 3) * 32;
    int n0 = (wid >> 2) * 64;
    int lr = lane & 7;
    int mi = lane >> 3;

    // ldmatrix base addresses (byte offsets advance by 32 per k16-step)
    uint32_t a0_addr = sb + A_HI + (uint32_t)(m0 + (mi & 1) * 8 + lr) * PITCH + (mi >> 1) * 16;
    uint32_t a1_addr = a0_addr + 16 * PITCH;
    uint32_t b_addr  = sb + W_HI + (uint32_t)(n0 + (mi >> 1) * 8 + lr) * PITCH + (mi & 1) * 16;

    float acc[2][8][4];
#pragma unroll
    for (int ti = 0; ti < 2; ti++)
#pragma unroll
        for (int tj = 0; tj < 8; tj++)
#pragma unroll
            for (int q = 0; q < 4; q++) acc[ti][tj][q] = 0.0f;

    for (int ks = 0; ks < 8; ks++) {
        uint32_t ko = ks * 32;
        uint32_t ah[2][4], al[2][4];
        ldsm_x4(ah[0], a0_addr + ko);
        ldsm_x4(ah[1], a1_addr + ko);
        ldsm_x4(al[0], a0_addr + (A_LO - A_HI) + ko);
        ldsm_x4(al[1], a1_addr + (A_LO - A_HI) + ko);
        uint32_t bh[8][2], bl[8][2];
#pragma unroll
        for (int q = 0; q < 4; q++) {
            ldsm_x4(&bh[2 * q][0], b_addr + q * 16 * PITCH + ko);
            ldsm_x4(&bl[2 * q][0], b_addr + (W_LO - W_HI) + q * 16 * PITCH + ko);
        }
#pragma unroll
        for (int ti = 0; ti < 2; ti++) {
#pragma unroll
            for (int tj = 0; tj < 8; tj++) {
                mma_bf16(acc[ti][tj], ah[ti], bh[tj]);
                mma_bf16(acc[ti][tj], ah[ti], bl[tj]);
                mma_bf16(acc[ti][tj], al[ti], bh[tj]);
            }
        }
    }

    // Epilogue: lane holds (r=lane/4, c=(lane%4)*2) and (r+8, c) per tile
    int rbase = row0 + m0 + (lane >> 2);
    int cbase = n0 + (lane & 3) * 2;
#pragma unroll
    for (int tj = 0; tj < 8; tj++) {
        int col = cbase + tj * 8;
        float b0 = sm_bias[col],   b1 = sm_bias[col + 1];
        float s0 = sm_sc[col],     s1 = sm_sc[col + 1];
        float h0 = sm_sh[col],     h1 = sm_sh[col + 1];
#pragma unroll
        for (int ti = 0; ti < 2; ti++) {
            int r = rbase + ti * 16;
            if (r < n) {
                float2 v;
                v.x = fmaxf(acc[ti][tj][0] + b0, 0.0f) * s0 + h0;
                v.y = fmaxf(acc[ti][tj][1] + b1, 0.0f) * s1 + h1;
                *(float2*)&C[(size_t)r * 128 + col] = v;
            }
            if (r + 8 < n) {
                float2 v;
                v.x = fmaxf(acc[ti][tj][2] + b0, 0.0f) * s0 + h0;
                v.y = fmaxf(acc[ti][tj][3] + b1, 0.0f) * s1 + h1;
                *(float2*)&C[(size_t)(r + 8) * 128 + col] = v;
            }
        }
    }
}

// ------------------------------ Pool + head ---------------------------------

__global__ void pool_kernel(const int* __restrict__ batch, int n, int g) {
    int t = blockIdx.x * blockDim.x + threadIdx.x;
    int node = t >> 5, seg = t & 31;
    if (node >= n) return;
    int gi = batch[node];
    if (gi < 0 || gi >= g) return;
    float4 v = ((const float4*)g_h)[(size_t)node * 32 + seg];
    float* p = &g_pooled[gi * 128 + seg * 4];
    atomicAdd(p + 0, v.x);
    atomicAdd(p + 1, v.y);
    atomicAdd(p + 2, v.z);
    atomicAdd(p + 3, v.w);
}

__global__ void head_kernel(const float* __restrict__ lin1W,
                            const float* __restrict__ lin1b,
                            const float* __restrict__ lin2W,
                            const float* __restrict__ lin2b,
                            float* __restrict__ out) {
    int g = blockIdx.x;
    int j = threadIdx.x;
    __shared__ float row[128];
    __shared__ float red[128];
    row[j] = g_pooled[g * 128 + j];
    __syncthreads();
    float acc = lin1b[j];
#pragma unroll 8
    for (int k = 0; k < 128; k++) acc = fmaf(row[k], lin1W[k * 128 + j], acc);
    acc = fmaxf(acc, 0.0f);
    red[j] = acc * lin2W[j];
    __syncthreads();
#pragma unroll
    for (int s = 64; s > 0; s >>= 1) {
        if (j < s) red[j] += red[j + s];
        __syncthreads();
    }
    if (j == 0) out[g] = red[0] + lin2b[0];
}

// ------------------------------- Launch --------------------------------------

extern "C" void kernel_launch(void* const* d_in, const int* in_sizes, int n_in,
                              void* d_out, int out_size) {
    const float* x     = (const float*)d_in[0];
    const int*   ei    = (const int*)d_in[1];
    const int*   batch = (const int*)d_in[2];
    const float* c1W1 = (const float*)d_in[3];
    const float* c1b1 = (const float*)d_in[4];
    const float* c1W2 = (const float*)d_in[5];
    const float* c1b2 = (const float*)d_in[6];
    const float* c1gm = (const float*)d_in[7];
    const float* c1bt = (const float*)d_in[8];
    const float* c1mn = (const float*)d_in[9];
    const float* c1vr = (const float*)d_in[10];
    const float* cW1  = (const float*)d_in[11];
    const float* cb1  = (const float*)d_in[12];
    const float* cW2  = (const float*)d_in[13];
    const float* cb2  = (const float*)d_in[14];
    const float* cgm  = (const float*)d_in[15];
    const float* cbt  = (const float*)d_in[16];
    const float* cmn  = (const float*)d_in[17];
    const float* cvr  = (const float*)d_in[18];
    const float* l1W  = (const float*)d_in[19];
    const float* l1b  = (const float*)d_in[20];
    const float* l2W  = (const float*)d_in[21];
    const float* l2b  = (const float*)d_in[22];
    float* out = (float*)d_out;

    int n = in_sizes[0] / 2;
    int e = in_sizes[1] / 2;
    int nl = in_sizes[11] / (HDIM * HDIM);
    int g = out_size;

    const int* src = ei;
    const int* dst = ei + e;

    float *p_h, *p_hpre, *p_h1;
    unsigned short* p_wprep;
    cudaGetSymbolAddress((void**)&p_h, g_h);
    cudaGetSymbolAddress((void**)&p_hpre, g_hpre);
    cudaGetSymbolAddress((void**)&p_h1, g_h1);
    cudaGetSymbolAddress((void**)&p_wprep, g_wprep);

    cudaFuncSetAttribute(gemm_tc, cudaFuncAttributeMaxDynamicSharedMemorySize,
                         GEMM_SMEM_BYTES);

    // Weight prep: slot0 = c1W2, slots 1..nl = cW1, slots 1+nl.. = cW2
    wprep_kernel<<<(1 * 16384 + 255) / 256, 256>>>(c1W2, 0, 1);
    wprep_kernel<<<(nl * 16384 + 255) / 256, 256>>>(cW1, 1, nl);
    wprep_kernel<<<(nl * 16384 + 255) / 256, 256>>>(cW2, 1 + nl, nl);

    // CSR build
    int zn = n > g * HDIM ? n : g * HDIM;
    zero_kernel<<<(zn + 255) / 256, 256>>>(n, g * HDIM);
    hist_kernel<<<(e + 255) / 256, 256>>>(dst, e, n);
    scan_kernel<<<1, 1024>>>(n);
    fill_kernel<<<(e + 255) / 256, 256>>>(src, dst, e, n);

    int gemm_blocks = (n + 127) / 128;
    int warp_grid = (n * 32 + 255) / 256;

    // Layer 0 (input dim 2)
    agg2_kernel<<<(n + 255) / 256, 256>>>(x, n);
    mlp0_kernel<<<warp_grid, 256>>>(c1W1, c1b1, n);
    gemm_tc<<<gemm_blocks, 256, GEMM_SMEM_BYTES>>>(
        p_h1, p_wprep, c1b2, c1gm, c1bt, c1mn, c1vr, p_h, n);

    // Layers 1..nl
    for (int i = 0; i < nl; i++) {
        agg_kernel<<<warp_grid, 256>>>(n);
        gemm_tc<<<gemm_blocks, 256, GEMM_SMEM_BYTES>>>(
            p_hpre, p_wprep + (size_t)(1 + i) * 32768,
            cb1 + (size_t)i * HDIM,
            nullptr, nullptr, nullptr, nullptr, p_h1, n);
        gemm_tc<<<gemm_blocks, 256, GEMM_SMEM_BYTES>>>(
            p_h1, p_wprep + (size_t)(1 + nl + i) * 32768,
            cb2 + (size_t)i * HDIM,
            cgm + (size_t)i * HDIM, cbt + (size_t)i * HDIM,
            cmn + (size_t)i * HDIM, cvr + (size_t)i * HDIM, p_h, n);
    }

    // Pool + head
    pool_kernel<<<warp_grid, 256>>>(batch, n, g);
    head_kernel<<<g, 128>>>(l1W, l1b, l2W, l2b, out);
}

// round 9
// speedup vs baseline: 1.0851x; 1.0851x over previous
#include <cuda_runtime.h>
#include <cstdint>

// ----------------------------------------------------------------------------
// GIN forward on GB300 (base sm_103 PTX): CSR gather aggregation (bf16 hi/lo
// split planes) + fused-MLP mma.sync bf16 3x-compensated GEMMs with cp.async
// operand staging, sorted-batch pooling, fused head.
// ----------------------------------------------------------------------------

#define NMAX 50048
#define EMAX 800000
#define HDIM 128
#define GMAX 512

__device__ float g_h[(size_t)NMAX * HDIM];            // layer output (fp32)
__device__ unsigned short g_hpre_hi[(size_t)NMAX * HDIM];  // agg out, bf16 hi
__device__ unsigned short g_hpre_lo[(size_t)NMAX * HDIM];  // agg out, bf16 lo
__device__ unsigned short g_h1_hi[(size_t)NMAX * HDIM];    // layer0 mlp1 out
__device__ unsigned short g_h1_lo[(size_t)NMAX * HDIM];
__device__ float g_hpre2[NMAX * 2];
__device__ int   g_deg[NMAX];
__device__ int   g_off[NMAX];
__device__ int   g_cnt[NMAX];
__device__ int   g_csr[EMAX];
__device__ float g_pooled[GMAX * HDIM];
// 9 weight mats x (hi plane 16384 + lo plane 16384) bf16, transposed [n][k]
__device__ unsigned short g_wprep[9 * 32768];

// ------------------------------ helpers -------------------------------------

__device__ __forceinline__ uint32_t smem_to_u32(const void* p) {
    uint32_t a;
    asm("{ .reg .u64 t; cvta.to.shared.u64 t, %1; cvt.u32.u64 %0, t; }"
        : "=r"(a) : "l"(p));
    return a;
}

// pack two floats to bf16x2: low half = first arg, high half = second arg
__device__ __forceinline__ uint32_t pack_bf16x2(float lo, float hi) {
    uint32_t r;
    asm("cvt.rn.bf16x2.f32 %0, %1, %2;" : "=r"(r) : "f"(hi), "f"(lo));
    return r;
}

__device__ __forceinline__ void ldsm_x4(uint32_t r[4], uint32_t addr) {
    asm volatile("ldmatrix.sync.aligned.m8n8.x4.shared.b16 {%0,%1,%2,%3}, [%4];"
                 : "=r"(r[0]), "=r"(r[1]), "=r"(r[2]), "=r"(r[3]) : "r"(addr));
}

__device__ __forceinline__ void mma_bf16(float c[4], const uint32_t a[4],
                                         const uint32_t b[2]) {
    asm volatile(
        "mma.sync.aligned.m16n8k16.row.col.f32.bf16.bf16.f32 "
        "{%0,%1,%2,%3}, {%4,%5,%6,%7}, {%8,%9}, {%0,%1,%2,%3};"
        : "+f"(c[0]), "+f"(c[1]), "+f"(c[2]), "+f"(c[3])
        : "r"(a[0]), "r"(a[1]), "r"(a[2]), "r"(a[3]), "r"(b[0]), "r"(b[1]));
}

__device__ __forceinline__ void cp16(uint32_t dst, const void* src) {
    asm volatile("cp.async.cg.shared.global [%0], [%1], 16;"
                 :: "r"(dst), "l"(src) : "memory");
}
#define CP_COMMIT() asm volatile("cp.async.commit_group;" ::: "memory")
#define CP_WAIT0()  asm volatile("cp.async.wait_group 0;" ::: "memory")
#define CP_WAIT1()  asm volatile("cp.async.wait_group 1;" ::: "memory")

// --------------------------- CSR construction -------------------------------

__global__ void zero_kernel(int n) {
    int i = blockIdx.x * blockDim.x + threadIdx.x;
    if (i < n) { g_deg[i] = 0; g_cnt[i] = 0; }
}

__global__ void hist_kernel(const int* __restrict__ dst, int e, int n) {
    int i = blockIdx.x * blockDim.x + threadIdx.x;
    if (i < e) {
        int d = dst[i];
        if (d >= 0 && d < n) atomicAdd(&g_deg[d], 1);
    }
}

__global__ void scan_kernel(int n) {
    __shared__ int sums[1024];
    int t = threadIdx.x;
    int chunk = (n + 1023) >> 10;
    int start = t * chunk;
    int end = start + chunk; if (end > n) end = n;
    int s = 0;
    for (int i = start; i < end; i++) s += g_deg[i];
    sums[t] = s;
    __syncthreads();
    for (int d = 1; d < 1024; d <<= 1) {
        int v = (t >= d) ? sums[t - d] : 0;
        __syncthreads();
        sums[t] += v;
        __syncthreads();
    }
    int run = (t == 0) ? 0 : sums[t - 1];
    for (int i = start; i < end; i++) { g_off[i] = run; run += g_deg[i]; }
}

__global__ void fill_kernel(const int* __restrict__ src,
                            const int* __restrict__ dst, int e, int n) {
    int i = blockIdx.x * blockDim.x + threadIdx.x;
    if (i < e) {
        int d = dst[i];
        int s = src[i];
        if (d >= 0 && d < n && s >= 0 && s < n) {
            int p = g_off[d] + atomicAdd(&g_cnt[d], 1);
            g_csr[p] = s;
        }
    }
}

// ----------------------- Weight prep (bf16 hi/lo, [n][k]) -------------------

__global__ void wprep_kernel(const float* __restrict__ src, int slot0, int nmat) {
    int i = blockIdx.x * blockDim.x + threadIdx.x;
    int total = nmat * 16384;
    if (i >= total) return;
    int m = i / 16384;
    int r = i - m * 16384;
    int k = r >> 7;
    int nn = r & 127;
    float v = src[i];                 // src[m][k][nn]
    uint32_t ph = pack_bf16x2(v, v);
    uint16_t hb = (uint16_t)(ph & 0xFFFFu);
    float hf = __uint_as_float((uint32_t)hb << 16);
    uint32_t pl = pack_bf16x2(v - hf, v - hf);
    uint16_t lb = (uint16_t)(pl & 0xFFFFu);
    int base = (slot0 + m) * 32768;
    g_wprep[base + nn * 128 + k] = hb;
    g_wprep[base + 16384 + nn * 128 + k] = lb;
}

// --------------------------- Layer 0 (d_in = 2) -----------------------------

__global__ void agg2_kernel(const float* __restrict__ x, int n) {
    int i = blockIdx.x * blockDim.x + threadIdx.x;
    if (i >= n) return;
    float a0 = x[i * 2], a1 = x[i * 2 + 1];
    int o = g_off[i], d = g_deg[i];
    for (int e = 0; e < d; e++) {
        int s = g_csr[o + e];
        a0 += x[s * 2];
        a1 += x[s * 2 + 1];
    }
    g_hpre2[i * 2] = a0;
    g_hpre2[i * 2 + 1] = a1;
}

// h1 = relu(hpre2 @ W1(2x128) + b1) -> bf16 hi/lo planes
__global__ void mlp0_kernel(const float* __restrict__ W1,
                            const float* __restrict__ b1, int n) {
    int t = blockIdx.x * blockDim.x + threadIdx.x;
    int node = t >> 5, seg = t & 31;
    if (node >= n) return;
    int c = seg * 4;
    float h0 = g_hpre2[node * 2];
    float h1v = g_hpre2[node * 2 + 1];
    float4 w0 = *(const float4*)&W1[c];
    float4 w1 = *(const float4*)&W1[HDIM + c];
    float4 bb = *(const float4*)&b1[c];
    float4 v;
    v.x = fmaxf(fmaf(h0, w0.x, fmaf(h1v, w1.x, bb.x)), 0.0f);
    v.y = fmaxf(fmaf(h0, w0.y, fmaf(h1v, w1.y, bb.y)), 0.0f);
    v.z = fmaxf(fmaf(h0, w0.z, fmaf(h1v, w1.z, bb.z)), 0.0f);
    v.w = fmaxf(fmaf(h0, w0.w, fmaf(h1v, w1.w, bb.w)), 0.0f);
    uint32_t hi01 = pack_bf16x2(v.x, v.y);
    uint32_t hi23 = pack_bf16x2(v.z, v.w);
    float hx = __uint_as_float(hi01 << 16);
    float hy = __uint_as_float(hi01 & 0xFFFF0000u);
    float hz = __uint_as_float(hi23 << 16);
    float hw = __uint_as_float(hi23 & 0xFFFF0000u);
    uint32_t lo01 = pack_bf16x2(v.x - hx, v.y - hy);
    uint32_t lo23 = pack_bf16x2(v.z - hz, v.w - hw);
    size_t idx = (size_t)node * HDIM + c;
    *(uint2*)&g_h1_hi[idx] = make_uint2(hi01, hi23);
    *(uint2*)&g_h1_lo[idx] = make_uint2(lo01, lo23);
}

// --------------------- Aggregation for 128-dim layers -----------------------
// warp per node; writes bf16 hi/lo planes (split done here, ALU is free)
__global__ void agg_kernel(int n) {
    int gt = blockIdx.x * blockDim.x + threadIdx.x;
    int node = gt >> 5, lane = gt & 31;
    if (node >= n) return;
    const float4* hp = (const float4*)g_h;
    float4 acc = hp[(size_t)node * 32 + lane];
    int o = g_off[node], d = g_deg[node];
    int e = 0;
    int d4 = d & ~3;
    for (; e < d4; e += 4) {
        int s0 = g_csr[o + e];
        int s1 = g_csr[o + e + 1];
        int s2 = g_csr[o + e + 2];
        int s3 = g_csr[o + e + 3];
        float4 v0 = hp[(size_t)s0 * 32 + lane];
        float4 v1 = hp[(size_t)s1 * 32 + lane];
        float4 v2 = hp[(size_t)s2 * 32 + lane];
        float4 v3 = hp[(size_t)s3 * 32 + lane];
        acc.x += v0.x + v1.x + v2.x + v3.x;
        acc.y += v0.y + v1.y + v2.y + v3.y;
        acc.z += v0.z + v1.z + v2.z + v3.z;
        acc.w += v0.w + v1.w + v2.w + v3.w;
    }
    for (; e < d; e++) {
        int s = g_csr[o + e];
        float4 v = hp[(size_t)s * 32 + lane];
        acc.x += v.x; acc.y += v.y; acc.z += v.z; acc.w += v.w;
    }
    uint32_t hi01 = pack_bf16x2(acc.x, acc.y);
    uint32_t hi23 = pack_bf16x2(acc.z, acc.w);
    float hx = __uint_as_float(hi01 << 16);
    float hy = __uint_as_float(hi01 & 0xFFFF0000u);
    float hz = __uint_as_float(hi23 << 16);
    float hw = __uint_as_float(hi23 & 0xFFFF0000u);
    uint32_t lo01 = pack_bf16x2(acc.x - hx, acc.y - hy);
    uint32_t lo23 = pack_bf16x2(acc.z - hz, acc.w - hw);
    size_t idx = (size_t)node * HDIM + lane * 4;
    *(uint2*)&g_hpre_hi[idx] = make_uint2(hi01, hi23);
    *(uint2*)&g_hpre_lo[idx] = make_uint2(lo01, lo23);
}

// ------------------- Fused MLP GEMM (and single-GEMM mode) ------------------
// smem: 0 b1[128], 512 b2, 1024 sc, 1536 sh, then 6 planes of 128x272B:
//   A_HI 2048, A_LO 36864, WA_HI 71680, WA_LO 106496, WB_HI 141312, WB_LO 176128
#define PITCH 272
#define PLANE 34816
#define A_HI 2048
#define WA_HI 71680
#define WB_HI 141312
#define GEMM_SMEM_BYTES 210944

__device__ __forceinline__ void mma_block(uint32_t a0, uint32_t a1, uint32_t bw,
                                          float acc[2][8][4]) {
#pragma unroll
    for (int ks = 0; ks < 8; ks++) {
        uint32_t ko = ks * 32;
        uint32_t ah[2][4], al[2][4];
        ldsm_x4(ah[0], a0 + ko);
        ldsm_x4(ah[1], a1 + ko);
        ldsm_x4(al[0], a0 + PLANE + ko);
        ldsm_x4(al[1], a1 + PLANE + ko);
        uint32_t bh[8][2], bl[8][2];
#pragma unroll
        for (int q = 0; q < 4; q++) {
            ldsm_x4(&bh[2 * q][0], bw + q * 16 * PITCH + ko);
            ldsm_x4(&bl[2 * q][0], bw + PLANE + q * 16 * PITCH + ko);
        }
#pragma unroll
        for (int ti = 0; ti < 2; ti++) {
#pragma unroll
            for (int tj = 0; tj < 8; tj++) {
                mma_bf16(acc[ti][tj], ah[ti], bh[tj]);
                mma_bf16(acc[ti][tj], ah[ti], bl[tj]);
                mma_bf16(acc[ti][tj], al[ti], bh[tj]);
            }
        }
    }
}

__global__ void __launch_bounds__(256)
gemm_mlp(const unsigned short* __restrict__ Ahi,
         const unsigned short* __restrict__ Alo,
         const unsigned short* __restrict__ W1p,   // nullptr => single GEMM
         const unsigned short* __restrict__ W2p,
         const float* __restrict__ b1, const float* __restrict__ b2,
         const float* __restrict__ gamma, const float* __restrict__ beta,
         const float* __restrict__ mean, const float* __restrict__ var,
         float* __restrict__ C, int n) {
    extern __shared__ __align__(16) char smem[];
    uint32_t sb = smem_to_u32(smem);
    int tid = threadIdx.x;
    int wid = tid >> 5;
    int lane = tid & 31;
    int row0 = blockIdx.x * 128;
    bool fused = (W1p != nullptr);

    // group 0: A planes + first W
#pragma unroll
    for (int it = 0; it < 16; it++) {
        int idx = it * 256 + tid;           // 0..4095
        int plane = idx >> 11;
        int r2 = idx & 2047;
        int row = r2 >> 4, cu = r2 & 15;
        const unsigned short* s = (plane ? Alo : Ahi) +
                                  ((size_t)(row0 + row) * 128 + cu * 8);
        cp16(sb + A_HI + plane * PLANE + row * PITCH + cu * 16, s);
    }
    const unsigned short* Wa = fused ? W1p : W2p;
#pragma unroll
    for (int it = 0; it < 16; it++) {
        int idx = it * 256 + tid;
        int plane = idx >> 11;
        int r2 = idx & 2047;
        int row = r2 >> 4, cu = r2 & 15;
        cp16(sb + WA_HI + plane * PLANE + row * PITCH + cu * 16,
             Wa + plane * 16384 + row * 128 + cu * 8);
    }
    CP_COMMIT();
    if (fused) {
        // group 1: W2 (overlaps gemm1)
#pragma unroll
        for (int it = 0; it < 16; it++) {
            int idx = it * 256 + tid;
            int plane = idx >> 11;
            int r2 = idx & 2047;
            int row = r2 >> 4, cu = r2 & 15;
            cp16(sb + WB_HI + plane * PLANE + row * PITCH + cu * 16,
                 W2p + plane * 16384 + row * 128 + cu * 8);
        }
        CP_COMMIT();
    }

    // epilogue params
    float* sm_b1 = (float*)(smem + 0);
    float* sm_b2 = (float*)(smem + 512);
    float* sm_sc = (float*)(smem + 1024);
    float* sm_sh = (float*)(smem + 1536);
    if (tid < 128) {
        sm_b1[tid] = fused ? b1[tid] : 0.0f;
        sm_b2[tid] = b2[tid];
        float scv = 1.0f, shv = 0.0f;
        if (gamma != nullptr) {
            scv = gamma[tid] * rsqrtf(var[tid] + 1e-5f);
            shv = beta[tid] - mean[tid] * scv;
        }
        sm_sc[tid] = scv; sm_sh[tid] = shv;
    }
    if (fused) { CP_WAIT1(); } else { CP_WAIT0(); }
    __syncthreads();

    int m0 = (wid & 3) * 32;
    int n0 = (wid >> 2) * 64;
    int lr = lane & 7;
    int mi = lane >> 3;
    uint32_t a0_addr = sb + A_HI + (uint32_t)(m0 + (mi & 1) * 8 + lr) * PITCH + (mi >> 1) * 16;
    uint32_t a1_addr = a0_addr + 16 * PITCH;
    uint32_t ba_addr = sb + WA_HI + (uint32_t)(n0 + (mi >> 1) * 8 + lr) * PITCH + (mi & 1) * 16;

    float acc[2][8][4];
#pragma unroll
    for (int ti = 0; ti < 2; ti++)
#pragma unroll
        for (int tj = 0; tj < 8; tj++)
#pragma unroll
            for (int q = 0; q < 4; q++) acc[ti][tj][q] = 0.0f;

    mma_block(a0_addr, a1_addr, ba_addr, acc);

    int rb = m0 + (lane >> 2);
    int cb = n0 + (lane & 3) * 2;

    if (fused) {
        __syncthreads();     // all warps done reading A/W1
        CP_WAIT0();          // W2 arrived (per-thread; syncthreads below publishes)
        // convert acc -> relu(acc+b1) -> bf16 hi/lo into A planes
#pragma unroll
        for (int tj = 0; tj < 8; tj++) {
            int col = cb + tj * 8;
            float bb0 = sm_b1[col], bb1 = sm_b1[col + 1];
#pragma unroll
            for (int ti = 0; ti < 2; ti++) {
                int r = rb + ti * 16;
                float v0 = fmaxf(acc[ti][tj][0] + bb0, 0.0f);
                float v1 = fmaxf(acc[ti][tj][1] + bb1, 0.0f);
                uint32_t hi = pack_bf16x2(v0, v1);
                float h0 = __uint_as_float(hi << 16);
                float h1 = __uint_as_float(hi & 0xFFFF0000u);
                uint32_t lo = pack_bf16x2(v0 - h0, v1 - h1);
                *(uint32_t*)(smem + A_HI + r * PITCH + col * 2) = hi;
                *(uint32_t*)(smem + A_HI + PLANE + r * PITCH + col * 2) = lo;
                float w0 = fmaxf(acc[ti][tj][2] + bb0, 0.0f);
                float w1 = fmaxf(acc[ti][tj][3] + bb1, 0.0f);
                uint32_t hi2 = pack_bf16x2(w0, w1);
                float g0 = __uint_as_float(hi2 << 16);
                float g1 = __uint_as_float(hi2 & 0xFFFF0000u);
                uint32_t lo2 = pack_bf16x2(w0 - g0, w1 - g1);
                *(uint32_t*)(smem + A_HI + (r + 8) * PITCH + col * 2) = hi2;
                *(uint32_t*)(smem + A_HI + PLANE + (r + 8) * PITCH + col * 2) = lo2;
                acc[ti][tj][0] = 0.0f; acc[ti][tj][1] = 0.0f;
                acc[ti][tj][2] = 0.0f; acc[ti][tj][3] = 0.0f;
            }
        }
        __syncthreads();
        uint32_t bb_addr = sb + WB_HI + (uint32_t)(n0 + (mi >> 1) * 8 + lr) * PITCH + (mi & 1) * 16;
        mma_block(a0_addr, a1_addr, bb_addr, acc);
    }

    // final epilogue: bias2, relu, BN affine -> C (fp32)
    int rbase = row0 + rb;
#pragma unroll
    for (int tj = 0; tj < 8; tj++) {
        int col = cb + tj * 8;
        float b0 = sm_b2[col], b1v = sm_b2[col + 1];
        float s0 = sm_sc[col], s1 = sm_sc[col + 1];
        float h0 = sm_sh[col], h1 = sm_sh[col + 1];
#pragma unroll
        for (int ti = 0; ti < 2; ti++) {
            int r = rbase + ti * 16;
            if (r < n) {
                float2 v;
                v.x = fmaxf(acc[ti][tj][0] + b0, 0.0f) * s0 + h0;
                v.y = fmaxf(acc[ti][tj][1] + b1v, 0.0f) * s1 + h1;
                *(float2*)&C[(size_t)r * 128 + col] = v;
            }
            if (r + 8 < n) {
                float2 v;
                v.x = fmaxf(acc[ti][tj][2] + b0, 0.0f) * s0 + h0;
                v.y = fmaxf(acc[ti][tj][3] + b1v, 0.0f) * s1 + h1;
                *(float2*)&C[(size_t)(r + 8) * 128 + col] = v;
            }
        }
    }
}

// ------------------------------ Pool + head ---------------------------------
// batch is sorted -> each graph is a contiguous node range; no atomics.
__global__ void pool_kernel(const int* __restrict__ batch, int n) {
    int gid = blockIdx.x;
    int j = threadIdx.x;
    __shared__ int se[2];
    if (j < 2) {
        int target = gid + j;
        int lo = 0, hi = n;
        while (lo < hi) {
            int mid = (lo + hi) >> 1;
            if (batch[mid] < target) lo = mid + 1; else hi = mid;
        }
        se[j] = lo;
    }
    __syncthreads();
    float acc = 0.0f;
    int s = se[0], e = se[1];
    for (int r = s; r < e; r++) acc += g_h[(size_t)r * HDIM + j];
    g_pooled[gid * HDIM + j] = acc;
}

__global__ void head_kernel(const float* __restrict__ lin1W,
                            const float* __restrict__ lin1b,
                            const float* __restrict__ lin2W,
                            const float* __restrict__ lin2b,
                            float* __restrict__ out) {
    int g = blockIdx.x;
    int j = threadIdx.x;
    __shared__ float row[128];
    __shared__ float red[128];
    row[j] = g_pooled[g * 128 + j];
    __syncthreads();
    float acc = lin1b[j];
#pragma unroll 8
    for (int k = 0; k < 128; k++) acc = fmaf(row[k], lin1W[k * 128 + j], acc);
    acc = fmaxf(acc, 0.0f);
    red[j] = acc * lin2W[j];
    __syncthreads();
#pragma unroll
    for (int s = 64; s > 0; s >>= 1) {
        if (j < s) red[j] += red[j + s];
        __syncthreads();
    }
    if (j == 0) out[g] = red[0] + lin2b[0];
}

// ------------------------------- Launch --------------------------------------

extern "C" void kernel_launch(void* const* d_in, const int* in_sizes, int n_in,
                              void* d_out, int out_size) {
    const float* x     = (const float*)d_in[0];
    const int*   ei    = (const int*)d_in[1];
    const int*   batch = (const int*)d_in[2];
    const float* c1W1 = (const float*)d_in[3];
    const float* c1b1 = (const float*)d_in[4];
    const float* c1W2 = (const float*)d_in[5];
    const float* c1b2 = (const float*)d_in[6];
    const float* c1gm = (const float*)d_in[7];
    const float* c1bt = (const float*)d_in[8];
    const float* c1mn = (const float*)d_in[9];
    const float* c1vr = (const float*)d_in[10];
    const float* cW1  = (const float*)d_in[11];
    const float* cb1  = (const float*)d_in[12];
    const float* cW2  = (const float*)d_in[13];
    const float* cb2  = (const float*)d_in[14];
    const float* cgm  = (const float*)d_in[15];
    const float* cbt  = (const float*)d_in[16];
    const float* cmn  = (const float*)d_in[17];
    const float* cvr  = (const float*)d_in[18];
    const float* l1W  = (const float*)d_in[19];
    const float* l1b  = (const float*)d_in[20];
    const float* l2W  = (const float*)d_in[21];
    const float* l2b  = (const float*)d_in[22];
    float* out = (float*)d_out;

    int n = in_sizes[0] / 2;
    int e = in_sizes[1] / 2;
    int nl = in_sizes[11] / (HDIM * HDIM);
    int g = out_size;

    const int* src = ei;
    const int* dst = ei + e;

    float* p_h;
    unsigned short *p_wprep, *p_hpre_hi, *p_hpre_lo, *p_h1_hi, *p_h1_lo;
    cudaGetSymbolAddress((void**)&p_h, g_h);
    cudaGetSymbolAddress((void**)&p_wprep, g_wprep);
    cudaGetSymbolAddress((void**)&p_hpre_hi, g_hpre_hi);
    cudaGetSymbolAddress((void**)&p_hpre_lo, g_hpre_lo);
    cudaGetSymbolAddress((void**)&p_h1_hi, g_h1_hi);
    cudaGetSymbolAddress((void**)&p_h1_lo, g_h1_lo);

    cudaFuncSetAttribute(gemm_mlp, cudaFuncAttributeMaxDynamicSharedMemorySize,
                         GEMM_SMEM_BYTES);

    // CSR build + weight prep
    zero_kernel<<<(n + 255) / 256, 256>>>(n);
    hist_kernel<<<(e + 255) / 256, 256>>>(dst, e, n);
    scan_kernel<<<1, 1024>>>(n);
    fill_kernel<<<(e + 255) / 256, 256>>>(src, dst, e, n);
    wprep_kernel<<<(1 * 16384 + 255) / 256, 256>>>(c1W2, 0, 1);
    wprep_kernel<<<(nl * 16384 + 255) / 256, 256>>>(cW1, 1, nl);
    wprep_kernel<<<(nl * 16384 + 255) / 256, 256>>>(cW2, 1 + nl, nl);

    int gemm_blocks = (n + 127) / 128;
    int warp_grid = (n * 32 + 255) / 256;

    // Layer 0 (input dim 2): agg2 -> mlp0 (split planes) -> single GEMM(W2)+BN
    agg2_kernel<<<(n + 255) / 256, 256>>>(x, n);
    mlp0_kernel<<<warp_grid, 256>>>(c1W1, c1b1, n);
    gemm_mlp<<<gemm_blocks, 256, GEMM_SMEM_BYTES>>>(
        p_h1_hi, p_h1_lo, nullptr, p_wprep, nullptr, c1b2,
        c1gm, c1bt, c1mn, c1vr, p_h, n);

    // Layers 1..nl: agg (split planes) -> fused MLP (2 GEMMs) + BN
    for (int i = 0; i < nl; i++) {
        agg_kernel<<<warp_grid, 256>>>(n);
        gemm_mlp<<<gemm_blocks, 256, GEMM_SMEM_BYTES>>>(
            p_hpre_hi, p_hpre_lo,
            p_wprep + (size_t)(1 + i) * 32768,
            p_wprep + (size_t)(1 + nl + i) * 32768,
            cb1 + (size_t)i * HDIM, cb2 + (size_t)i * HDIM,
            cgm + (size_t)i * HDIM, cbt + (size_t)i * HDIM,
            cmn + (size_t)i * HDIM, cvr + (size_t)i * HDIM, p_h, n);
    }

    // Pool (sorted batch, no atomics) + head
    pool_kernel<<<g, 128>>>(batch, n);
    head_kernel<<<g, 128>>>(l1W, l1b, l2W, l2b, out);
}

// round 10
// speedup vs baseline: 1.0851x; 1.0001x over previous
#include <cuda_runtime.h>
#include <cstdint>

// ----------------------------------------------------------------------------
// GIN forward on GB300 (base sm_103 PTX): CSR gather aggregation (bf16 hi/lo
// split planes) + fused-MLP mma.sync bf16 3x-compensated GEMMs with cp.async
// operand staging, sorted-batch pooling, fused head.
// ----------------------------------------------------------------------------

#define NMAX 50048
#define EMAX 800000
#define HDIM 128
#define GMAX 512

__device__ float g_h[(size_t)NMAX * HDIM];            // layer output (fp32)
__device__ unsigned short g_hpre_hi[(size_t)NMAX * HDIM];  // agg out, bf16 hi
__device__ unsigned short g_hpre_lo[(size_t)NMAX * HDIM];  // agg out, bf16 lo
__device__ unsigned short g_h1_hi[(size_t)NMAX * HDIM];    // layer0 mlp1 out
__device__ unsigned short g_h1_lo[(size_t)NMAX * HDIM];
__device__ float g_hpre2[NMAX * 2];
__device__ int   g_deg[NMAX];
__device__ int   g_off[NMAX];
__device__ int   g_cnt[NMAX];
__device__ int   g_csr[EMAX];
__device__ float g_pooled[GMAX * HDIM];
// 9 weight mats x (hi plane 16384 + lo plane 16384) bf16, transposed [n][k]
__device__ unsigned short g_wprep[9 * 32768];

// ------------------------------ helpers -------------------------------------

__device__ __forceinline__ uint32_t smem_to_u32(const void* p) {
    uint32_t a;
    asm("{ .reg .u64 t; cvta.to.shared.u64 t, %1; cvt.u32.u64 %0, t; }"
        : "=r"(a) : "l"(p));
    return a;
}

// pack two floats to bf16x2: low half = first arg, high half = second arg
__device__ __forceinline__ uint32_t pack_bf16x2(float lo, float hi) {
    uint32_t r;
    asm("cvt.rn.bf16x2.f32 %0, %1, %2;" : "=r"(r) : "f"(hi), "f"(lo));
    return r;
}

__device__ __forceinline__ void ldsm_x4(uint32_t r[4], uint32_t addr) {
    asm volatile("ldmatrix.sync.aligned.m8n8.x4.shared.b16 {%0,%1,%2,%3}, [%4];"
                 : "=r"(r[0]), "=r"(r[1]), "=r"(r[2]), "=r"(r[3]) : "r"(addr));
}

__device__ __forceinline__ void mma_bf16(float c[4], const uint32_t a[4],
                                         const uint32_t b[2]) {
    asm volatile(
        "mma.sync.aligned.m16n8k16.row.col.f32.bf16.bf16.f32 "
        "{%0,%1,%2,%3}, {%4,%5,%6,%7}, {%8,%9}, {%0,%1,%2,%3};"
        : "+f"(c[0]), "+f"(c[1]), "+f"(c[2]), "+f"(c[3])
        : "r"(a[0]), "r"(a[1]), "r"(a[2]), "r"(a[3]), "r"(b[0]), "r"(b[1]));
}

__device__ __forceinline__ void cp16(uint32_t dst, const void* src) {
    asm volatile("cp.async.cg.shared.global [%0], [%1], 16;"
                 :: "r"(dst), "l"(src) : "memory");
}
#define CP_COMMIT() asm volatile("cp.async.commit_group;" ::: "memory")
#define CP_WAIT0()  asm volatile("cp.async.wait_group 0;" ::: "memory")
#define CP_WAIT1()  asm volatile("cp.async.wait_group 1;" ::: "memory")

// --------------------------- CSR construction -------------------------------

__global__ void zero_kernel(int n) {
    int i = blockIdx.x * blockDim.x + threadIdx.x;
    if (i < n) { g_deg[i] = 0; g_cnt[i] = 0; }
}

__global__ void hist_kernel(const int* __restrict__ dst, int e, int n) {
    int i = blockIdx.x * blockDim.x + threadIdx.x;
    if (i < e) {
        int d = dst[i];
        if (d >= 0 && d < n) atomicAdd(&g_deg[d], 1);
    }
}

__global__ void scan_kernel(int n) {
    __shared__ int sums[1024];
    int t = threadIdx.x;
    int chunk = (n + 1023) >> 10;
    int start = t * chunk;
    int end = start + chunk; if (end > n) end = n;
    int s = 0;
    for (int i = start; i < end; i++) s += g_deg[i];
    sums[t] = s;
    __syncthreads();
    for (int d = 1; d < 1024; d <<= 1) {
        int v = (t >= d) ? sums[t - d] : 0;
        __syncthreads();
        sums[t] += v;
        __syncthreads();
    }
    int run = (t == 0) ? 0 : sums[t - 1];
    for (int i = start; i < end; i++) { g_off[i] = run; run += g_deg[i]; }
}

__global__ void fill_kernel(const int* __restrict__ src,
                            const int* __restrict__ dst, int e, int n) {
    int i = blockIdx.x * blockDim.x + threadIdx.x;
    if (i < e) {
        int d = dst[i];
        int s = src[i];
        if (d >= 0 && d < n && s >= 0 && s < n) {
            int p = g_off[d] + atomicAdd(&g_cnt[d], 1);
            g_csr[p] = s;
        }
    }
}

// ----------------------- Weight prep (bf16 hi/lo, [n][k]) -------------------

__global__ void wprep_kernel(const float* __restrict__ src, int slot0, int nmat) {
    int i = blockIdx.x * blockDim.x + threadIdx.x;
    int total = nmat * 16384;
    if (i >= total) return;
    int m = i / 16384;
    int r = i - m * 16384;
    int k = r >> 7;
    int nn = r & 127;
    float v = src[i];                 // src[m][k][nn]
    uint32_t ph = pack_bf16x2(v, v);
    uint16_t hb = (uint16_t)(ph & 0xFFFFu);
    float hf = __uint_as_float((uint32_t)hb << 16);
    uint32_t pl = pack_bf16x2(v - hf, v - hf);
    uint16_t lb = (uint16_t)(pl & 0xFFFFu);
    int base = (slot0 + m) * 32768;
    g_wprep[base + nn * 128 + k] = hb;
    g_wprep[base + 16384 + nn * 128 + k] = lb;
}

// --------------------------- Layer 0 (d_in = 2) -----------------------------

__global__ void agg2_kernel(const float* __restrict__ x, int n) {
    int i = blockIdx.x * blockDim.x + threadIdx.x;
    if (i >= n) return;
    float a0 = x[i * 2], a1 = x[i * 2 + 1];
    int o = g_off[i], d = g_deg[i];
    for (int e = 0; e < d; e++) {
        int s = g_csr[o + e];
        a0 += x[s * 2];
        a1 += x[s * 2 + 1];
    }
    g_hpre2[i * 2] = a0;
    g_hpre2[i * 2 + 1] = a1;
}

// h1 = relu(hpre2 @ W1(2x128) + b1) -> bf16 hi/lo planes
__global__ void mlp0_kernel(const float* __restrict__ W1,
                            const float* __restrict__ b1, int n) {
    int t = blockIdx.x * blockDim.x + threadIdx.x;
    int node = t >> 5, seg = t & 31;
    if (node >= n) return;
    int c = seg * 4;
    float h0 = g_hpre2[node * 2];
    float h1v = g_hpre2[node * 2 + 1];
    float4 w0 = *(const float4*)&W1[c];
    float4 w1 = *(const float4*)&W1[HDIM + c];
    float4 bb = *(const float4*)&b1[c];
    float4 v;
    v.x = fmaxf(fmaf(h0, w0.x, fmaf(h1v, w1.x, bb.x)), 0.0f);
    v.y = fmaxf(fmaf(h0, w0.y, fmaf(h1v, w1.y, bb.y)), 0.0f);
    v.z = fmaxf(fmaf(h0, w0.z, fmaf(h1v, w1.z, bb.z)), 0.0f);
    v.w = fmaxf(fmaf(h0, w0.w, fmaf(h1v, w1.w, bb.w)), 0.0f);
    uint32_t hi01 = pack_bf16x2(v.x, v.y);
    uint32_t hi23 = pack_bf16x2(v.z, v.w);
    float hx = __uint_as_float(hi01 << 16);
    float hy = __uint_as_float(hi01 & 0xFFFF0000u);
    float hz = __uint_as_float(hi23 << 16);
    float hw = __uint_as_float(hi23 & 0xFFFF0000u);
    uint32_t lo01 = pack_bf16x2(v.x - hx, v.y - hy);
    uint32_t lo23 = pack_bf16x2(v.z - hz, v.w - hw);
    size_t idx = (size_t)node * HDIM + c;
    *(uint2*)&g_h1_hi[idx] = make_uint2(hi01, hi23);
    *(uint2*)&g_h1_lo[idx] = make_uint2(lo01, lo23);
}

// --------------------- Aggregation for 128-dim layers -----------------------
// warp per node; writes bf16 hi/lo planes (split done here, ALU is free)
__global__ void agg_kernel(int n) {
    int gt = blockIdx.x * blockDim.x + threadIdx.x;
    int node = gt >> 5, lane = gt & 31;
    if (node >= n) return;
    const float4* hp = (const float4*)g_h;
    float4 acc = hp[(size_t)node * 32 + lane];
    int o = g_off[node], d = g_deg[node];
    int e = 0;
    int d4 = d & ~3;
    for (; e < d4; e += 4) {
        int s0 = g_csr[o + e];
        int s1 = g_csr[o + e + 1];
        int s2 = g_csr[o + e + 2];
        int s3 = g_csr[o + e + 3];
        float4 v0 = hp[(size_t)s0 * 32 + lane];
        float4 v1 = hp[(size_t)s1 * 32 + lane];
        float4 v2 = hp[(size_t)s2 * 32 + lane];
        float4 v3 = hp[(size_t)s3 * 32 + lane];
        acc.x += v0.x + v1.x + v2.x + v3.x;
        acc.y += v0.y + v1.y + v2.y + v3.y;
        acc.z += v0.z + v1.z + v2.z + v3.z;
        acc.w += v0.w + v1.w + v2.w + v3.w;
    }
    for (; e < d; e++) {
        int s = g_csr[o + e];
        float4 v = hp[(size_t)s * 32 + lane];
        acc.x += v.x; acc.y += v.y; acc.z += v.z; acc.w += v.w;
    }
    uint32_t hi01 = pack_bf16x2(acc.x, acc.y);
    uint32_t hi23 = pack_bf16x2(acc.z, acc.w);
    float hx = __uint_as_float(hi01 << 16);
    float hy = __uint_as_float(hi01 & 0xFFFF0000u);
    float hz = __uint_as_float(hi23 << 16);
    float hw = __uint_as_float(hi23 & 0xFFFF0000u);
    uint32_t lo01 = pack_bf16x2(acc.x - hx, acc.y - hy);
    uint32_t lo23 = pack_bf16x2(acc.z - hz, acc.w - hw);
    size_t idx = (size_t)node * HDIM + lane * 4;
    *(uint2*)&g_hpre_hi[idx] = make_uint2(hi01, hi23);
    *(uint2*)&g_hpre_lo[idx] = make_uint2(lo01, lo23);
}

// ------------------- Fused MLP GEMM (and single-GEMM mode) ------------------
// smem: 0 b1[128], 512 b2, 1024 sc, 1536 sh, then 6 planes of 128x272B:
//   A_HI 2048, A_LO 36864, WA_HI 71680, WA_LO 106496, WB_HI 141312, WB_LO 176128
#define PITCH 272
#define PLANE 34816
#define A_HI 2048
#define WA_HI 71680
#define WB_HI 141312
#define GEMM_SMEM_BYTES 210944

__device__ __forceinline__ void mma_block(uint32_t a0, uint32_t a1, uint32_t bw,
                                          float acc[2][8][4]) {
#pragma unroll
    for (int ks = 0; ks < 8; ks++) {
        uint32_t ko = ks * 32;
        uint32_t ah[2][4], al[2][4];
        ldsm_x4(ah[0], a0 + ko);
        ldsm_x4(ah[1], a1 + ko);
        ldsm_x4(al[0], a0 + PLANE + ko);
        ldsm_x4(al[1], a1 + PLANE + ko);
        uint32_t bh[8][2], bl[8][2];
#pragma unroll
        for (int q = 0; q < 4; q++) {
            ldsm_x4(&bh[2 * q][0], bw + q * 16 * PITCH + ko);
            ldsm_x4(&bl[2 * q][0], bw + PLANE + q * 16 * PITCH + ko);
        }
#pragma unroll
        for (int ti = 0; ti < 2; ti++) {
#pragma unroll
            for (int tj = 0; tj < 8; tj++) {
                mma_bf16(acc[ti][tj], ah[ti], bh[tj]);
                mma_bf16(acc[ti][tj], ah[ti], bl[tj]);
                mma_bf16(acc[ti][tj], al[ti], bh[tj]);
            }
        }
    }
}

__global__ void __launch_bounds__(256)
gemm_mlp(const unsigned short* __restrict__ Ahi,
         const unsigned short* __restrict__ Alo,
         const unsigned short* __restrict__ W1p,   // nullptr => single GEMM
         const unsigned short* __restrict__ W2p,
         const float* __restrict__ b1, const float* __restrict__ b2,
         const float* __restrict__ gamma, const float* __restrict__ beta,
         const float* __restrict__ mean, const float* __restrict__ var,
         float* __restrict__ C, int n) {
    extern __shared__ __align__(16) char smem[];
    uint32_t sb = smem_to_u32(smem);
    int tid = threadIdx.x;
    int wid = tid >> 5;
    int lane = tid & 31;
    int row0 = blockIdx.x * 128;
    bool fused = (W1p != nullptr);

    // group 0: A planes + first W
#pragma unroll
    for (int it = 0; it < 16; it++) {
        int idx = it * 256 + tid;           // 0..4095
        int plane = idx >> 11;
        int r2 = idx & 2047;
        int row = r2 >> 4, cu = r2 & 15;
        const unsigned short* s = (plane ? Alo : Ahi) +
                                  ((size_t)(row0 + row) * 128 + cu * 8);
        cp16(sb + A_HI + plane * PLANE + row * PITCH + cu * 16, s);
    }
    const unsigned short* Wa = fused ? W1p : W2p;
#pragma unroll
    for (int it = 0; it < 16; it++) {
        int idx = it * 256 + tid;
        int plane = idx >> 11;
        int r2 = idx & 2047;
        int row = r2 >> 4, cu = r2 & 15;
        cp16(sb + WA_HI + plane * PLANE + row * PITCH + cu * 16,
             Wa + plane * 16384 + row * 128 + cu * 8);
    }
    CP_COMMIT();
    if (fused) {
        // group 1: W2 (overlaps gemm1)
#pragma unroll
        for (int it = 0; it < 16; it++) {
            int idx = it * 256 + tid;
            int plane = idx >> 11;
            int r2 = idx & 2047;
            int row = r2 >> 4, cu = r2 & 15;
            cp16(sb + WB_HI + plane * PLANE + row * PITCH + cu * 16,
                 W2p + plane * 16384 + row * 128 + cu * 8);
        }
        CP_COMMIT();
    }

    // epilogue params
    float* sm_b1 = (float*)(smem + 0);
    float* sm_b2 = (float*)(smem + 512);
    float* sm_sc = (float*)(smem + 1024);
    float* sm_sh = (float*)(smem + 1536);
    if (tid < 128) {
        sm_b1[tid] = fused ? b1[tid] : 0.0f;
        sm_b2[tid] = b2[tid];
        float scv = 1.0f, shv = 0.0f;
        if (gamma != nullptr) {
            scv = gamma[tid] * rsqrtf(var[tid] + 1e-5f);
            shv = beta[tid] - mean[tid] * scv;
        }
        sm_sc[tid] = scv; sm_sh[tid] = shv;
    }
    if (fused) { CP_WAIT1(); } else { CP_WAIT0(); }
    __syncthreads();

    int m0 = (wid & 3) * 32;
    int n0 = (wid >> 2) * 64;
    int lr = lane & 7;
    int mi = lane >> 3;
    uint32_t a0_addr = sb + A_HI + (uint32_t)(m0 + (mi & 1) * 8 + lr) * PITCH + (mi >> 1) * 16;
    uint32_t a1_addr = a0_addr + 16 * PITCH;
    uint32_t ba_addr = sb + WA_HI + (uint32_t)(n0 + (mi >> 1) * 8 + lr) * PITCH + (mi & 1) * 16;

    float acc[2][8][4];
#pragma unroll
    for (int ti = 0; ti < 2; ti++)
#pragma unroll
        for (int tj = 0; tj < 8; tj++)
#pragma unroll
            for (int q = 0; q < 4; q++) acc[ti][tj][q] = 0.0f;

    mma_block(a0_addr, a1_addr, ba_addr, acc);

    int rb = m0 + (lane >> 2);
    int cb = n0 + (lane & 3) * 2;

    if (fused) {
        __syncthreads();     // all warps done reading A/W1
        CP_WAIT0();          // W2 arrived (per-thread; syncthreads below publishes)
        // convert acc -> relu(acc+b1) -> bf16 hi/lo into A planes
#pragma unroll
        for (int tj = 0; tj < 8; tj++) {
            int col = cb + tj * 8;
            float bb0 = sm_b1[col], bb1 = sm_b1[col + 1];
#pragma unroll
            for (int ti = 0; ti < 2; ti++) {
                int r = rb + ti * 16;
                float v0 = fmaxf(acc[ti][tj][0] + bb0, 0.0f);
                float v1 = fmaxf(acc[ti][tj][1] + bb1, 0.0f);
                uint32_t hi = pack_bf16x2(v0, v1);
                float h0 = __uint_as_float(hi << 16);
                float h1 = __uint_as_float(hi & 0xFFFF0000u);
                uint32_t lo = pack_bf16x2(v0 - h0, v1 - h1);
                *(uint32_t*)(smem + A_HI + r * PITCH + col * 2) = hi;
                *(uint32_t*)(smem + A_HI + PLANE + r * PITCH + col * 2) = lo;
                float w0 = fmaxf(acc[ti][tj][2] + bb0, 0.0f);
                float w1 = fmaxf(acc[ti][tj][3] + bb1, 0.0f);
                uint32_t hi2 = pack_bf16x2(w0, w1);
                float g0 = __uint_as_float(hi2 << 16);
                float g1 = __uint_as_float(hi2 & 0xFFFF0000u);
                uint32_t lo2 = pack_bf16x2(w0 - g0, w1 - g1);
                *(uint32_t*)(smem + A_HI + (r + 8) * PITCH + col * 2) = hi2;
                *(uint32_t*)(smem + A_HI + PLANE + (r + 8) * PITCH + col * 2) = lo2;
                acc[ti][tj][0] = 0.0f; acc[ti][tj][1] = 0.0f;
                acc[ti][tj][2] = 0.0f; acc[ti][tj][3] = 0.0f;
            }
        }
        __syncthreads();
        uint32_t bb_addr = sb + WB_HI + (uint32_t)(n0 + (mi >> 1) * 8 + lr) * PITCH + (mi & 1) * 16;
        mma_block(a0_addr, a1_addr, bb_addr, acc);
    }

    // final epilogue: bias2, relu, BN affine -> C (fp32)
    int rbase = row0 + rb;
#pragma unroll
    for (int tj = 0; tj < 8; tj++) {
        int col = cb + tj * 8;
        float b0 = sm_b2[col], b1v = sm_b2[col + 1];
        float s0 = sm_sc[col], s1 = sm_sc[col + 1];
        float h0 = sm_sh[col], h1 = sm_sh[col + 1];
#pragma unroll
        for (int ti = 0; ti < 2; ti++) {
            int r = rbase + ti * 16;
            if (r < n) {
                float2 v;
                v.x = fmaxf(acc[ti][tj][0] + b0, 0.0f) * s0 + h0;
                v.y = fmaxf(acc[ti][tj][1] + b1v, 0.0f) * s1 + h1;
                *(float2*)&C[(size_t)r * 128 + col] = v;
            }
            if (r + 8 < n) {
                float2 v;
                v.x = fmaxf(acc[ti][tj][2] + b0, 0.0f) * s0 + h0;
                v.y = fmaxf(acc[ti][tj][3] + b1v, 0.0f) * s1 + h1;
                *(float2*)&C[(size_t)(r + 8) * 128 + col] = v;
            }
        }
    }
}

// ------------------------------ Pool + head ---------------------------------
// batch is sorted -> each graph is a contiguous node range; no atomics.
__global__ void pool_kernel(const int* __restrict__ batch, int n) {
    int gid = blockIdx.x;
    int j = threadIdx.x;
    __shared__ int se[2];
    if (j < 2) {
        int target = gid + j;
        int lo = 0, hi = n;
        while (lo < hi) {
            int mid = (lo + hi) >> 1;
            if (batch[mid] < target) lo = mid + 1; else hi = mid;
        }
        se[j] = lo;
    }
    __syncthreads();
    float acc = 0.0f;
    int s = se[0], e = se[1];
    for (int r = s; r < e; r++) acc += g_h[(size_t)r * HDIM + j];
    g_pooled[gid * HDIM + j] = acc;
}

__global__ void head_kernel(const float* __restrict__ lin1W,
                            const float* __restrict__ lin1b,
                            const float* __restrict__ lin2W,
                            const float* __restrict__ lin2b,
                            float* __restrict__ out) {
    int g = blockIdx.x;
    int j = threadIdx.x;
    __shared__ float row[128];
    __shared__ float red[128];
    row[j] = g_pooled[g * 128 + j];
    __syncthreads();
    float acc = lin1b[j];
#pragma unroll 8
    for (int k = 0; k < 128; k++) acc = fmaf(row[k], lin1W[k * 128 + j], acc);
    acc = fmaxf(acc, 0.0f);
    red[j] = acc * lin2W[j];
    __syncthreads();
#pragma unroll
    for (int s = 64; s > 0; s >>= 1) {
        if (j < s) red[j] += red[j + s];
        __syncthreads();
    }
    if (j == 0) out[g] = red[0] + lin2b[0];
}

// ------------------------------- Launch --------------------------------------

extern "C" void kernel_launch(void* const* d_in, const int* in_sizes, int n_in,
                              void* d_out, int out_size) {
    const float* x     = (const float*)d_in[0];
    const int*   ei    = (const int*)d_in[1];
    const int*   batch = (const int*)d_in[2];
    const float* c1W1 = (const float*)d_in[3];
    const float* c1b1 = (const float*)d_in[4];
    const float* c1W2 = (const float*)d_in[5];
    const float* c1b2 = (const float*)d_in[6];
    const float* c1gm = (const float*)d_in[7];
    const float* c1bt = (const float*)d_in[8];
    const float* c1mn = (const float*)d_in[9];
    const float* c1vr = (const float*)d_in[10];
    const float* cW1  = (const float*)d_in[11];
    const float* cb1  = (const float*)d_in[12];
    const float* cW2  = (const float*)d_in[13];
    const float* cb2  = (const float*)d_in[14];
    const float* cgm  = (const float*)d_in[15];
    const float* cbt  = (const float*)d_in[16];
    const float* cmn  = (const float*)d_in[17];
    const float* cvr  = (const float*)d_in[18];
    const float* l1W  = (const float*)d_in[19];
    const float* l1b  = (const float*)d_in[20];
    const float* l2W  = (const float*)d_in[21];
    const float* l2b  = (const float*)d_in[22];
    float* out = (float*)d_out;

    int n = in_sizes[0] / 2;
    int e = in_sizes[1] / 2;
    int nl = in_sizes[11] / (HDIM * HDIM);
    int g = out_size;

    const int* src = ei;
    const int* dst = ei + e;

    float* p_h;
    unsigned short *p_wprep, *p_hpre_hi, *p_hpre_lo, *p_h1_hi, *p_h1_lo;
    cudaGetSymbolAddress((void**)&p_h, g_h);
    cudaGetSymbolAddress((void**)&p_wprep, g_wprep);
    cudaGetSymbolAddress((void**)&p_hpre_hi, g_hpre_hi);
    cudaGetSymbolAddress((void**)&p_hpre_lo, g_hpre_lo);
    cudaGetSymbolAddress((void**)&p_h1_hi, g_h1_hi);
    cudaGetSymbolAddress((void**)&p_h1_lo, g_h1_lo);

    cudaFuncSetAttribute(gemm_mlp, cudaFuncAttributeMaxDynamicSharedMemorySize,
                         GEMM_SMEM_BYTES);

    // CSR build + weight prep
    zero_kernel<<<(n + 255) / 256, 256>>>(n);
    hist_kernel<<<(e + 255) / 256, 256>>>(dst, e, n);
    scan_kernel<<<1, 1024>>>(n);
    fill_kernel<<<(e + 255) / 256, 256>>>(src, dst, e, n);
    wprep_kernel<<<(1 * 16384 + 255) / 256, 256>>>(c1W2, 0, 1);
    wprep_kernel<<<(nl * 16384 + 255) / 256, 256>>>(cW1, 1, nl);
    wprep_kernel<<<(nl * 16384 + 255) / 256, 256>>>(cW2, 1 + nl, nl);

    int gemm_blocks = (n + 127) / 128;
    int warp_grid = (n * 32 + 255) / 256;

    // Layer 0 (input dim 2): agg2 -> mlp0 (split planes) -> single GEMM(W2)+BN
    agg2_kernel<<<(n + 255) / 256, 256>>>(x, n);
    mlp0_kernel<<<warp_grid, 256>>>(c1W1, c1b1, n);
    gemm_mlp<<<gemm_blocks, 256, GEMM_SMEM_BYTES>>>(
        p_h1_hi, p_h1_lo, nullptr, p_wprep, nullptr, c1b2,
        c1gm, c1bt, c1mn, c1vr, p_h, n);

    // Layers 1..nl: agg (split planes) -> fused MLP (2 GEMMs) + BN
    for (int i = 0; i < nl; i++) {
        agg_kernel<<<warp_grid, 256>>>(n);
        gemm_mlp<<<gemm_blocks, 256, GEMM_SMEM_BYTES>>>(
            p_hpre_hi, p_hpre_lo,
            p_wprep + (size_t)(1 + i) * 32768,
            p_wprep + (size_t)(1 + nl + i) * 32768,
            cb1 + (size_t)i * HDIM, cb2 + (size_t)i * HDIM,
            cgm + (size_t)i * HDIM, cbt + (size_t)i * HDIM,
            cmn + (size_t)i * HDIM, cvr + (size_t)i * HDIM, p_h, n);
    }

    // Pool (sorted batch, no atomics) + head
    pool_kernel<<<g, 128>>>(batch, n);
    head_kernel<<<g, 128>>>(l1W, l1b, l2W, l2b, out);
}

// round 11
// speedup vs baseline: 1.0955x; 1.0095x over previous
#include <cuda_runtime.h>
#include <cstdint>

// ----------------------------------------------------------------------------
// GIN forward on GB300 (base sm_103 PTX): CSR gather aggregation (bf16 hi/lo
// split planes) + fused-MLP mma.sync bf16 3x-compensated GEMMs with cp.async
// operand staging, sorted-batch pooling, fused head.
// ----------------------------------------------------------------------------

#define NMAX 50048
#define EMAX 800000
#define HDIM 128
#define GMAX 512

__device__ float g_h[(size_t)NMAX * HDIM];            // layer output (fp32)
__device__ unsigned short g_hpre_hi[(size_t)NMAX * HDIM];  // agg out, bf16 hi
__device__ unsigned short g_hpre_lo[(size_t)NMAX * HDIM];  // agg out, bf16 lo
__device__ unsigned short g_h1_hi[(size_t)NMAX * HDIM];    // layer0 mlp1 out
__device__ unsigned short g_h1_lo[(size_t)NMAX * HDIM];
__device__ float g_hpre2[NMAX * 2];
__device__ int   g_deg[NMAX];
__device__ int   g_off[NMAX];
__device__ int   g_cnt[NMAX];
__device__ int   g_csr[EMAX];
__device__ float g_pooled[GMAX * HDIM];
// 9 weight mats x (hi plane 16384 + lo plane 16384) bf16, transposed [n][k]
__device__ unsigned short g_wprep[9 * 32768];

// ------------------------------ helpers -------------------------------------

__device__ __forceinline__ uint32_t smem_to_u32(const void* p) {
    uint32_t a;
    asm("{ .reg .u64 t; cvta.to.shared.u64 t, %1; cvt.u32.u64 %0, t; }"
        : "=r"(a) : "l"(p));
    return a;
}

// pack two floats to bf16x2: low half = first arg, high half = second arg
__device__ __forceinline__ uint32_t pack_bf16x2(float lo, float hi) {
    uint32_t r;
    asm("cvt.rn.bf16x2.f32 %0, %1, %2;" : "=r"(r) : "f"(hi), "f"(lo));
    return r;
}

__device__ __forceinline__ void ldsm_x4(uint32_t r[4], uint32_t addr) {
    asm volatile("ldmatrix.sync.aligned.m8n8.x4.shared.b16 {%0,%1,%2,%3}, [%4];"
                 : "=r"(r[0]), "=r"(r[1]), "=r"(r[2]), "=r"(r[3]) : "r"(addr));
}

__device__ __forceinline__ void mma_bf16(float c[4], const uint32_t a[4],
                                         const uint32_t b[2]) {
    asm volatile(
        "mma.sync.aligned.m16n8k16.row.col.f32.bf16.bf16.f32 "
        "{%0,%1,%2,%3}, {%4,%5,%6,%7}, {%8,%9}, {%0,%1,%2,%3};"
        : "+f"(c[0]), "+f"(c[1]), "+f"(c[2]), "+f"(c[3])
        : "r"(a[0]), "r"(a[1]), "r"(a[2]), "r"(a[3]), "r"(b[0]), "r"(b[1]));
}

__device__ __forceinline__ void cp16(uint32_t dst, const void* src) {
    asm volatile("cp.async.cg.shared.global [%0], [%1], 16;"
                 :: "r"(dst), "l"(src) : "memory");
}
#define CP_COMMIT() asm volatile("cp.async.commit_group;" ::: "memory")
#define CP_WAIT0()  asm volatile("cp.async.wait_group 0;" ::: "memory")
#define CP_WAIT1()  asm volatile("cp.async.wait_group 1;" ::: "memory")

// --------------------------- CSR construction -------------------------------

__global__ void zero_kernel(int n) {
    int i = blockIdx.x * blockDim.x + threadIdx.x;
    if (i < n) { g_deg[i] = 0; g_cnt[i] = 0; }
}

__global__ void hist_kernel(const int* __restrict__ dst, int e, int n) {
    int i = blockIdx.x * blockDim.x + threadIdx.x;
    if (i < e) {
        int d = dst[i];
        if (d >= 0 && d < n) atomicAdd(&g_deg[d], 1);
    }
}

__global__ void scan_kernel(int n) {
    __shared__ int sums[1024];
    int t = threadIdx.x;
    int chunk = (n + 1023) >> 10;
    int start = t * chunk;
    int end = start + chunk; if (end > n) end = n;
    int s = 0;
    for (int i = start; i < end; i++) s += g_deg[i];
    sums[t] = s;
    __syncthreads();
    for (int d = 1; d < 1024; d <<= 1) {
        int v = (t >= d) ? sums[t - d] : 0;
        __syncthreads();
        sums[t] += v;
        __syncthreads();
    }
    int run = (t == 0) ? 0 : sums[t - 1];
    for (int i = start; i < end; i++) { g_off[i] = run; run += g_deg[i]; }
}

__global__ void fill_kernel(const int* __restrict__ src,
                            const int* __restrict__ dst, int e, int n) {
    int i = blockIdx.x * blockDim.x + threadIdx.x;
    if (i < e) {
        int d = dst[i];
        int s = src[i];
        if (d >= 0 && d < n && s >= 0 && s < n) {
            int p = g_off[d] + atomicAdd(&g_cnt[d], 1);
            g_csr[p] = s;
        }
    }
}

// ----------------------- Weight prep (bf16 hi/lo, [n][k]) -------------------

__global__ void wprep_kernel(const float* __restrict__ src, int slot0, int nmat) {
    int i = blockIdx.x * blockDim.x + threadIdx.x;
    int total = nmat * 16384;
    if (i >= total) return;
    int m = i / 16384;
    int r = i - m * 16384;
    int k = r >> 7;
    int nn = r & 127;
    float v = src[i];                 // src[m][k][nn]
    uint32_t ph = pack_bf16x2(v, v);
    uint16_t hb = (uint16_t)(ph & 0xFFFFu);
    float hf = __uint_as_float((uint32_t)hb << 16);
    uint32_t pl = pack_bf16x2(v - hf, v - hf);
    uint16_t lb = (uint16_t)(pl & 0xFFFFu);
    int base = (slot0 + m) * 32768;
    g_wprep[base + nn * 128 + k] = hb;
    g_wprep[base + 16384 + nn * 128 + k] = lb;
}

// --------------------------- Layer 0 (d_in = 2) -----------------------------

__global__ void agg2_kernel(const float* __restrict__ x, int n) {
    int i = blockIdx.x * blockDim.x + threadIdx.x;
    if (i >= n) return;
    float a0 = x[i * 2], a1 = x[i * 2 + 1];
    int o = g_off[i], d = g_deg[i];
    for (int e = 0; e < d; e++) {
        int s = g_csr[o + e];
        a0 += x[s * 2];
        a1 += x[s * 2 + 1];
    }
    g_hpre2[i * 2] = a0;
    g_hpre2[i * 2 + 1] = a1;
}

// h1 = relu(hpre2 @ W1(2x128) + b1) -> bf16 hi/lo planes
__global__ void mlp0_kernel(const float* __restrict__ W1,
                            const float* __restrict__ b1, int n) {
    int t = blockIdx.x * blockDim.x + threadIdx.x;
    int node = t >> 5, seg = t & 31;
    if (node >= n) return;
    int c = seg * 4;
    float h0 = g_hpre2[node * 2];
    float h1v = g_hpre2[node * 2 + 1];
    float4 w0 = *(const float4*)&W1[c];
    float4 w1 = *(const float4*)&W1[HDIM + c];
    float4 bb = *(const float4*)&b1[c];
    float4 v;
    v.x = fmaxf(fmaf(h0, w0.x, fmaf(h1v, w1.x, bb.x)), 0.0f);
    v.y = fmaxf(fmaf(h0, w0.y, fmaf(h1v, w1.y, bb.y)), 0.0f);
    v.z = fmaxf(fmaf(h0, w0.z, fmaf(h1v, w1.z, bb.z)), 0.0f);
    v.w = fmaxf(fmaf(h0, w0.w, fmaf(h1v, w1.w, bb.w)), 0.0f);
    uint32_t hi01 = pack_bf16x2(v.x, v.y);
    uint32_t hi23 = pack_bf16x2(v.z, v.w);
    float hx = __uint_as_float(hi01 << 16);
    float hy = __uint_as_float(hi01 & 0xFFFF0000u);
    float hz = __uint_as_float(hi23 << 16);
    float hw = __uint_as_float(hi23 & 0xFFFF0000u);
    uint32_t lo01 = pack_bf16x2(v.x - hx, v.y - hy);
    uint32_t lo23 = pack_bf16x2(v.z - hz, v.w - hw);
    size_t idx = (size_t)node * HDIM + c;
    *(uint2*)&g_h1_hi[idx] = make_uint2(hi01, hi23);
    *(uint2*)&g_h1_lo[idx] = make_uint2(lo01, lo23);
}

// --------------------- Aggregation for 128-dim layers -----------------------
// warp per node; writes bf16 hi/lo planes (split done here, ALU is free)
__global__ void agg_kernel(int n) {
    int gt = blockIdx.x * blockDim.x + threadIdx.x;
    int node = gt >> 5, lane = gt & 31;
    if (node >= n) return;
    const float4* hp = (const float4*)g_h;
    float4 acc = hp[(size_t)node * 32 + lane];
    int o = g_off[node], d = g_deg[node];
    int e = 0;
    int d4 = d & ~3;
    for (; e < d4; e += 4) {
        int s0 = g_csr[o + e];
        int s1 = g_csr[o + e + 1];
        int s2 = g_csr[o + e + 2];
        int s3 = g_csr[o + e + 3];
        float4 v0 = hp[(size_t)s0 * 32 + lane];
        float4 v1 = hp[(size_t)s1 * 32 + lane];
        float4 v2 = hp[(size_t)s2 * 32 + lane];
        float4 v3 = hp[(size_t)s3 * 32 + lane];
        acc.x += v0.x + v1.x + v2.x + v3.x;
        acc.y += v0.y + v1.y + v2.y + v3.y;
        acc.z += v0.z + v1.z + v2.z + v3.z;
        acc.w += v0.w + v1.w + v2.w + v3.w;
    }
    for (; e < d; e++) {
        int s = g_csr[o + e];
        float4 v = hp[(size_t)s * 32 + lane];
        acc.x += v.x; acc.y += v.y; acc.z += v.z; acc.w += v.w;
    }
    uint32_t hi01 = pack_bf16x2(acc.x, acc.y);
    uint32_t hi23 = pack_bf16x2(acc.z, acc.w);
    float hx = __uint_as_float(hi01 << 16);
    float hy = __uint_as_float(hi01 & 0xFFFF0000u);
    float hz = __uint_as_float(hi23 << 16);
    float hw = __uint_as_float(hi23 & 0xFFFF0000u);
    uint32_t lo01 = pack_bf16x2(acc.x - hx, acc.y - hy);
    uint32_t lo23 = pack_bf16x2(acc.z - hz, acc.w - hw);
    size_t idx = (size_t)node * HDIM + lane * 4;
    *(uint2*)&g_hpre_hi[idx] = make_uint2(hi01, hi23);
    *(uint2*)&g_hpre_lo[idx] = make_uint2(lo01, lo23);
}

// ------------------- Fused MLP GEMM (and single-GEMM mode) ------------------
// smem: 0 b1[128], 512 b2, 1024 sc, 1536 sh, then 6 planes of 128x272B:
//   A_HI 2048, A_LO 36864, WA_HI 71680, WA_LO 106496, WB_HI 141312, WB_LO 176128
#define PITCH 272
#define PLANE 34816
#define A_HI 2048
#define WA_HI 71680
#define WB_HI 141312
#define GEMM_SMEM_BYTES 210944

__device__ __forceinline__ void mma_block(uint32_t a0, uint32_t a1, uint32_t bw,
                                          float acc[2][8][4]) {
#pragma unroll
    for (int ks = 0; ks < 8; ks++) {
        uint32_t ko = ks * 32;
        uint32_t ah[2][4], al[2][4];
        ldsm_x4(ah[0], a0 + ko);
        ldsm_x4(ah[1], a1 + ko);
        ldsm_x4(al[0], a0 + PLANE + ko);
        ldsm_x4(al[1], a1 + PLANE + ko);
        uint32_t bh[8][2], bl[8][2];
#pragma unroll
        for (int q = 0; q < 4; q++) {
            ldsm_x4(&bh[2 * q][0], bw + q * 16 * PITCH + ko);
            ldsm_x4(&bl[2 * q][0], bw + PLANE + q * 16 * PITCH + ko);
        }
#pragma unroll
        for (int ti = 0; ti < 2; ti++) {
#pragma unroll
            for (int tj = 0; tj < 8; tj++) {
                mma_bf16(acc[ti][tj], ah[ti], bh[tj]);
                mma_bf16(acc[ti][tj], ah[ti], bl[tj]);
                mma_bf16(acc[ti][tj], al[ti], bh[tj]);
            }
        }
    }
}

__global__ void __launch_bounds__(256)
gemm_mlp(const unsigned short* __restrict__ Ahi,
         const unsigned short* __restrict__ Alo,
         const unsigned short* __restrict__ W1p,   // nullptr => single GEMM
         const unsigned short* __restrict__ W2p,
         const float* __restrict__ b1, const float* __restrict__ b2,
         const float* __restrict__ gamma, const float* __restrict__ beta,
         const float* __restrict__ mean, const float* __restrict__ var,
         float* __restrict__ C, int n) {
    extern __shared__ __align__(16) char smem[];
    uint32_t sb = smem_to_u32(smem);
    int tid = threadIdx.x;
    int wid = tid >> 5;
    int lane = tid & 31;
    int row0 = blockIdx.x * 128;
    bool fused = (W1p != nullptr);

    // group 0: A planes + first W
#pragma unroll
    for (int it = 0; it < 16; it++) {
        int idx = it * 256 + tid;           // 0..4095
        int plane = idx >> 11;
        int r2 = idx & 2047;
        int row = r2 >> 4, cu = r2 & 15;
        const unsigned short* s = (plane ? Alo : Ahi) +
                                  ((size_t)(row0 + row) * 128 + cu * 8);
        cp16(sb + A_HI + plane * PLANE + row * PITCH + cu * 16, s);
    }
    const unsigned short* Wa = fused ? W1p : W2p;
#pragma unroll
    for (int it = 0; it < 16; it++) {
        int idx = it * 256 + tid;
        int plane = idx >> 11;
        int r2 = idx & 2047;
        int row = r2 >> 4, cu = r2 & 15;
        cp16(sb + WA_HI + plane * PLANE + row * PITCH + cu * 16,
             Wa + plane * 16384 + row * 128 + cu * 8);
    }
    CP_COMMIT();
    if (fused) {
        // group 1: W2 (overlaps gemm1)
#pragma unroll
        for (int it = 0; it < 16; it++) {
            int idx = it * 256 + tid;
            int plane = idx >> 11;
            int r2 = idx & 2047;
            int row = r2 >> 4, cu = r2 & 15;
            cp16(sb + WB_HI + plane * PLANE + row * PITCH + cu * 16,
                 W2p + plane * 16384 + row * 128 + cu * 8);
        }
        CP_COMMIT();
    }

    // epilogue params
    float* sm_b1 = (float*)(smem + 0);
    float* sm_b2 = (float*)(smem + 512);
    float* sm_sc = (float*)(smem + 1024);
    float* sm_sh = (float*)(smem + 1536);
    if (tid < 128) {
        sm_b1[tid] = fused ? b1[tid] : 0.0f;
        sm_b2[tid] = b2[tid];
        float scv = 1.0f, shv = 0.0f;
        if (gamma != nullptr) {
            scv = gamma[tid] * rsqrtf(var[tid] + 1e-5f);
            shv = beta[tid] - mean[tid] * scv;
        }
        sm_sc[tid] = scv; sm_sh[tid] = shv;
    }
    if (fused) { CP_WAIT1(); } else { CP_WAIT0(); }
    __syncthreads();

    int m0 = (wid & 3) * 32;
    int n0 = (wid >> 2) * 64;
    int lr = lane & 7;
    int mi = lane >> 3;
    uint32_t a0_addr = sb + A_HI + (uint32_t)(m0 + (mi & 1) * 8 + lr) * PITCH + (mi >> 1) * 16;
    uint32_t a1_addr = a0_addr + 16 * PITCH;
    uint32_t ba_addr = sb + WA_HI + (uint32_t)(n0 + (mi >> 1) * 8 + lr) * PITCH + (mi & 1) * 16;

    float acc[2][8][4];
#pragma unroll
    for (int ti = 0; ti < 2; ti++)
#pragma unroll
        for (int tj = 0; tj < 8; tj++)
#pragma unroll
            for (int q = 0; q < 4; q++) acc[ti][tj][q] = 0.0f;

    mma_block(a0_addr, a1_addr, ba_addr, acc);

    int rb = m0 + (lane >> 2);
    int cb = n0 + (lane & 3) * 2;

    if (fused) {
        __syncthreads();     // all warps done reading A/W1
        CP_WAIT0();          // W2 arrived (per-thread; syncthreads below publishes)
        // convert acc -> relu(acc+b1) -> bf16 hi/lo into A planes
#pragma unroll
        for (int tj = 0; tj < 8; tj++) {
            int col = cb + tj * 8;
            float bb0 = sm_b1[col], bb1 = sm_b1[col + 1];
#pragma unroll
            for (int ti = 0; ti < 2; ti++) {
                int r = rb + ti * 16;
                float v0 = fmaxf(acc[ti][tj][0] + bb0, 0.0f);
                float v1 = fmaxf(acc[ti][tj][1] + bb1, 0.0f);
                uint32_t hi = pack_bf16x2(v0, v1);
                float h0 = __uint_as_float(hi << 16);
                float h1 = __uint_as_float(hi & 0xFFFF0000u);
                uint32_t lo = pack_bf16x2(v0 - h0, v1 - h1);
                *(uint32_t*)(smem + A_HI + r * PITCH + col * 2) = hi;
                *(uint32_t*)(smem + A_HI + PLANE + r * PITCH + col * 2) = lo;
                float w0 = fmaxf(acc[ti][tj][2] + bb0, 0.0f);
                float w1 = fmaxf(acc[ti][tj][3] + bb1, 0.0f);
                uint32_t hi2 = pack_bf16x2(w0, w1);
                float g0 = __uint_as_float(hi2 << 16);
                float g1 = __uint_as_float(hi2 & 0xFFFF0000u);
                uint32_t lo2 = pack_bf16x2(w0 - g0, w1 - g1);
                *(uint32_t*)(smem + A_HI + (r + 8) * PITCH + col * 2) = hi2;
                *(uint32_t*)(smem + A_HI + PLANE + (r + 8) * PITCH + col * 2) = lo2;
                acc[ti][tj][0] = 0.0f; acc[ti][tj][1] = 0.0f;
                acc[ti][tj][2] = 0.0f; acc[ti][tj][3] = 0.0f;
            }
        }
        __syncthreads();
        uint32_t bb_addr = sb + WB_HI + (uint32_t)(n0 + (mi >> 1) * 8 + lr) * PITCH + (mi & 1) * 16;
        mma_block(a0_addr, a1_addr, bb_addr, acc);
    }

    // final epilogue: bias2, relu, BN affine -> C (fp32)
    int rbase = row0 + rb;
#pragma unroll
    for (int tj = 0; tj < 8; tj++) {
        int col = cb + tj * 8;
        float b0 = sm_b2[col], b1v = sm_b2[col + 1];
        float s0 = sm_sc[col], s1 = sm_sc[col + 1];
        float h0 = sm_sh[col], h1 = sm_sh[col + 1];
#pragma unroll
        for (int ti = 0; ti < 2; ti++) {
            int r = rbase + ti * 16;
            if (r < n) {
                float2 v;
                v.x = fmaxf(acc[ti][tj][0] + b0, 0.0f) * s0 + h0;
                v.y = fmaxf(acc[ti][tj][1] + b1v, 0.0f) * s1 + h1;
                *(float2*)&C[(size_t)r * 128 + col] = v;
            }
            if (r + 8 < n) {
                float2 v;
                v.x = fmaxf(acc[ti][tj][2] + b0, 0.0f) * s0 + h0;
                v.y = fmaxf(acc[ti][tj][3] + b1v, 0.0f) * s1 + h1;
                *(float2*)&C[(size_t)(r + 8) * 128 + col] = v;
            }
        }
    }
}

// ------------------------------ Pool + head ---------------------------------
// batch is sorted -> each graph is a contiguous node range; no atomics.
__global__ void pool_kernel(const int* __restrict__ batch, int n) {
    int gid = blockIdx.x;
    int j = threadIdx.x;
    __shared__ int se[2];
    if (j < 2) {
        int target = gid + j;
        int lo = 0, hi = n;
        while (lo < hi) {
            int mid = (lo + hi) >> 1;
            if (batch[mid] < target) lo = mid + 1; else hi = mid;
        }
        se[j] = lo;
    }
    __syncthreads();
    float acc = 0.0f;
    int s = se[0], e = se[1];
    for (int r = s; r < e; r++) acc += g_h[(size_t)r * HDIM + j];
    g_pooled[gid * HDIM + j] = acc;
}

__global__ void head_kernel(const float* __restrict__ lin1W,
                            const float* __restrict__ lin1b,
                            const float* __restrict__ lin2W,
                            const float* __restrict__ lin2b,
                            float* __restrict__ out) {
    int g = blockIdx.x;
    int j = threadIdx.x;
    __shared__ float row[128];
    __shared__ float red[128];
    row[j] = g_pooled[g * 128 + j];
    __syncthreads();
    float acc = lin1b[j];
#pragma unroll 8
    for (int k = 0; k < 128; k++) acc = fmaf(row[k], lin1W[k * 128 + j], acc);
    acc = fmaxf(acc, 0.0f);
    red[j] = acc * lin2W[j];
    __syncthreads();
#pragma unroll
    for (int s = 64; s > 0; s >>= 1) {
        if (j < s) red[j] += red[j + s];
        __syncthreads();
    }
    if (j == 0) out[g] = red[0] + lin2b[0];
}

// ------------------------------- Launch --------------------------------------

extern "C" void kernel_launch(void* const* d_in, const int* in_sizes, int n_in,
                              void* d_out, int out_size) {
    const float* x     = (const float*)d_in[0];
    const int*   ei    = (const int*)d_in[1];
    const int*   batch = (const int*)d_in[2];
    const float* c1W1 = (const float*)d_in[3];
    const float* c1b1 = (const float*)d_in[4];
    const float* c1W2 = (const float*)d_in[5];
    const float* c1b2 = (const float*)d_in[6];
    const float* c1gm = (const float*)d_in[7];
    const float* c1bt = (const float*)d_in[8];
    const float* c1mn = (const float*)d_in[9];
    const float* c1vr = (const float*)d_in[10];
    const float* cW1  = (const float*)d_in[11];
    const float* cb1  = (const float*)d_in[12];
    const float* cW2  = (const float*)d_in[13];
    const float* cb2  = (const float*)d_in[14];
    const float* cgm  = (const float*)d_in[15];
    const float* cbt  = (const float*)d_in[16];
    const float* cmn  = (const float*)d_in[17];
    const float* cvr  = (const float*)d_in[18];
    const float* l1W  = (const float*)d_in[19];
    const float* l1b  = (const float*)d_in[20];
    const float* l2W  = (const float*)d_in[21];
    const float* l2b  = (const float*)d_in[22];
    float* out = (float*)d_out;

    int n = in_sizes[0] / 2;
    int e = in_sizes[1] / 2;
    int nl = in_sizes[11] / (HDIM * HDIM);
    int g = out_size;

    const int* src = ei;
    const int* dst = ei + e;

    float* p_h;
    unsigned short *p_wprep, *p_hpre_hi, *p_hpre_lo, *p_h1_hi, *p_h1_lo;
    cudaGetSymbolAddress((void**)&p_h, g_h);
    cudaGetSymbolAddress((void**)&p_wprep, g_wprep);
    cudaGetSymbolAddress((void**)&p_hpre_hi, g_hpre_hi);
    cudaGetSymbolAddress((void**)&p_hpre_lo, g_hpre_lo);
    cudaGetSymbolAddress((void**)&p_h1_hi, g_h1_hi);
    cudaGetSymbolAddress((void**)&p_h1_lo, g_h1_lo);

    cudaFuncSetAttribute(gemm_mlp, cudaFuncAttributeMaxDynamicSharedMemorySize,
                         GEMM_SMEM_BYTES);

    // CSR build + weight prep
    zero_kernel<<<(n + 255) / 256, 256>>>(n);
    hist_kernel<<<(e + 255) / 256, 256>>>(dst, e, n);
    scan_kernel<<<1, 1024>>>(n);
    fill_kernel<<<(e + 255) / 256, 256>>>(src, dst, e, n);
    wprep_kernel<<<(1 * 16384 + 255) / 256, 256>>>(c1W2, 0, 1);
    wprep_kernel<<<(nl * 16384 + 255) / 256, 256>>>(cW1, 1, nl);
    wprep_kernel<<<(nl * 16384 + 255) / 256, 256>>>(cW2, 1 + nl, nl);

    int gemm_blocks = (n + 127) / 128;
    int warp_grid = (n * 32 + 255) / 256;

    // Layer 0 (input dim 2): agg2 -> mlp0 (split planes) -> single GEMM(W2)+BN
    agg2_kernel<<<(n + 255) / 256, 256>>>(x, n);
    mlp0_kernel<<<warp_grid, 256>>>(c1W1, c1b1, n);
    gemm_mlp<<<gemm_blocks, 256, GEMM_SMEM_BYTES>>>(
        p_h1_hi, p_h1_lo, nullptr, p_wprep, nullptr, c1b2,
        c1gm, c1bt, c1mn, c1vr, p_h, n);

    // Layers 1..nl: agg (split planes) -> fused MLP (2 GEMMs) + BN
    for (int i = 0; i < nl; i++) {
        agg_kernel<<<warp_grid, 256>>>(n);
        gemm_mlp<<<gemm_blocks, 256, GEMM_SMEM_BYTES>>>(
            p_hpre_hi, p_hpre_lo,
            p_wprep + (size_t)(1 + i) * 32768,
            p_wprep + (size_t)(1 + nl + i) * 32768,
            cb1 + (size_t)i * HDIM, cb2 + (size_t)i * HDIM,
            cgm + (size_t)i * HDIM, cbt + (size_t)i * HDIM,
            cmn + (size_t)i * HDIM, cvr + (size_t)i * HDIM, p_h, n);
    }

    // Pool (sorted batch, no atomics) + head
    pool_kernel<<<g, 128>>>(batch, n);
    head_kernel<<<g, 128>>>(l1W, l1b, l2W, l2b, out);
}

// round 12
// speedup vs baseline: 1.2430x; 1.1346x over previous
#include <cuda_runtime.h>
#include <cuda_fp16.h>
#include <cstdint>

// ----------------------------------------------------------------------------
// GIN forward on GB300 (base sm_103 PTX): CSR gather aggregation over fp16
// node features (halved L2 traffic) + fused-MLP mma.sync bf16 3x-compensated
// GEMMs with cp.async staging, fused pool+head.
// ----------------------------------------------------------------------------

#define NMAX 50048
#define EMAX 800000
#define HDIM 128
#define GMAX 512

__device__ __half g_h[(size_t)NMAX * HDIM];                // layer output (fp16)
__device__ unsigned short g_hpre_hi[(size_t)NMAX * HDIM];  // agg out, bf16 hi
__device__ unsigned short g_hpre_lo[(size_t)NMAX * HDIM];  // agg out, bf16 lo
__device__ unsigned short g_h1_hi[(size_t)NMAX * HDIM];    // layer0 mlp1 out
__device__ unsigned short g_h1_lo[(size_t)NMAX * HDIM];
__device__ int   g_deg[NMAX];
__device__ int   g_off[NMAX];
__device__ int   g_cnt[NMAX];
__device__ int   g_csr[EMAX];
// 9 weight mats x (hi plane 16384 + lo plane 16384) bf16, transposed [n][k]
__device__ unsigned short g_wprep[9 * 32768];

// ------------------------------ helpers -------------------------------------

__device__ __forceinline__ uint32_t smem_to_u32(const void* p) {
    uint32_t a;
    asm("{ .reg .u64 t; cvta.to.shared.u64 t, %1; cvt.u32.u64 %0, t; }"
        : "=r"(a) : "l"(p));
    return a;
}

__device__ __forceinline__ uint32_t pack_bf16x2(float lo, float hi) {
    uint32_t r;
    asm("cvt.rn.bf16x2.f32 %0, %1, %2;" : "=r"(r) : "f"(hi), "f"(lo));
    return r;
}

__device__ __forceinline__ void ldsm_x4(uint32_t r[4], uint32_t addr) {
    asm volatile("ldmatrix.sync.aligned.m8n8.x4.shared.b16 {%0,%1,%2,%3}, [%4];"
                 : "=r"(r[0]), "=r"(r[1]), "=r"(r[2]), "=r"(r[3]) : "r"(addr));
}

__device__ __forceinline__ void mma_bf16(float c[4], const uint32_t a[4],
                                         const uint32_t b[2]) {
    asm volatile(
        "mma.sync.aligned.m16n8k16.row.col.f32.bf16.bf16.f32 "
        "{%0,%1,%2,%3}, {%4,%5,%6,%7}, {%8,%9}, {%0,%1,%2,%3};"
        : "+f"(c[0]), "+f"(c[1]), "+f"(c[2]), "+f"(c[3])
        : "r"(a[0]), "r"(a[1]), "r"(a[2]), "r"(a[3]), "r"(b[0]), "r"(b[1]));
}

__device__ __forceinline__ void cp16(uint32_t dst, const void* src) {
    asm volatile("cp.async.cg.shared.global [%0], [%1], 16;"
                 :: "r"(dst), "l"(src) : "memory");
}
#define CP_COMMIT() asm volatile("cp.async.commit_group;" ::: "memory")
#define CP_WAIT0()  asm volatile("cp.async.wait_group 0;" ::: "memory")
#define CP_WAIT1()  asm volatile("cp.async.wait_group 1;" ::: "memory")

__device__ __forceinline__ float4 h4_to_f4(uint2 r) {
    __half2 p0 = *reinterpret_cast<__half2*>(&r.x);
    __half2 p1 = *reinterpret_cast<__half2*>(&r.y);
    float2 f0 = __half22float2(p0);
    float2 f1 = __half22float2(p1);
    return make_float4(f0.x, f0.y, f1.x, f1.y);
}

// --------------------------- CSR construction -------------------------------

__global__ void zero_kernel(int n) {
    int i = blockIdx.x * blockDim.x + threadIdx.x;
    if (i < n) { g_deg[i] = 0; g_cnt[i] = 0; }
}

__global__ void hist_kernel(const int* __restrict__ dst, int e, int n) {
    int i = blockIdx.x * blockDim.x + threadIdx.x;
    if (i < e) {
        int d = dst[i];
        if (d >= 0 && d < n) atomicAdd(&g_deg[d], 1);
    }
}

__global__ void scan_kernel(int n) {
    __shared__ int sums[1024];
    int t = threadIdx.x;
    int chunk = (n + 1023) >> 10;
    int start = t * chunk;
    int end = start + chunk; if (end > n) end = n;
    int s = 0;
    for (int i = start; i < end; i++) s += g_deg[i];
    sums[t] = s;
    __syncthreads();
    for (int d = 1; d < 1024; d <<= 1) {
        int v = (t >= d) ? sums[t - d] : 0;
        __syncthreads();
        sums[t] += v;
        __syncthreads();
    }
    int run = (t == 0) ? 0 : sums[t - 1];
    for (int i = start; i < end; i++) { g_off[i] = run; run += g_deg[i]; }
}

__global__ void fill_kernel(const int* __restrict__ src,
                            const int* __restrict__ dst, int e, int n) {
    int i = blockIdx.x * blockDim.x + threadIdx.x;
    if (i < e) {
        int d = dst[i];
        int s = src[i];
        if (d >= 0 && d < n && s >= 0 && s < n) {
            int p = g_off[d] + atomicAdd(&g_cnt[d], 1);
            g_csr[p] = s;
        }
    }
}

// ----------------------- Weight prep (bf16 hi/lo, [n][k]) -------------------

__global__ void wprep_kernel(const float* __restrict__ src, int slot0, int nmat) {
    int i = blockIdx.x * blockDim.x + threadIdx.x;
    int total = nmat * 16384;
    if (i >= total) return;
    int m = i / 16384;
    int r = i - m * 16384;
    int k = r >> 7;
    int nn = r & 127;
    float v = src[i];                 // src[m][k][nn]
    uint32_t ph = pack_bf16x2(v, v);
    uint16_t hb = (uint16_t)(ph & 0xFFFFu);
    float hf = __uint_as_float((uint32_t)hb << 16);
    uint32_t pl = pack_bf16x2(v - hf, v - hf);
    uint16_t lb = (uint16_t)(pl & 0xFFFFu);
    int base = (slot0 + m) * 32768;
    g_wprep[base + nn * 128 + k] = hb;
    g_wprep[base + 16384 + nn * 128 + k] = lb;
}

// -------------- Layer 0: fused agg(dim2) + MLP1 (warp per node) -------------

__global__ void agg_mlp0_kernel(const float* __restrict__ x,
                                const float* __restrict__ W1,
                                const float* __restrict__ b1, int n) {
    int gt = blockIdx.x * blockDim.x + threadIdx.x;
    int node = gt >> 5, lane = gt & 31;
    if (node >= n) return;
    int o = g_off[node], d = g_deg[node];
    float a0 = 0.0f, a1 = 0.0f;
    for (int e = lane; e < d; e += 32) {
        int s = g_csr[o + e];
        float2 v = *(const float2*)&x[s * 2];
        a0 += v.x; a1 += v.y;
    }
#pragma unroll
    for (int m = 16; m > 0; m >>= 1) {
        a0 += __shfl_xor_sync(0xFFFFFFFFu, a0, m);
        a1 += __shfl_xor_sync(0xFFFFFFFFu, a1, m);
    }
    float2 self = *(const float2*)&x[node * 2];
    a0 += self.x; a1 += self.y;

    int c = lane * 4;
    float4 w0 = *(const float4*)&W1[c];
    float4 w1 = *(const float4*)&W1[HDIM + c];
    float4 bb = *(const float4*)&b1[c];
    float4 v;
    v.x = fmaxf(fmaf(a0, w0.x, fmaf(a1, w1.x, bb.x)), 0.0f);
    v.y = fmaxf(fmaf(a0, w0.y, fmaf(a1, w1.y, bb.y)), 0.0f);
    v.z = fmaxf(fmaf(a0, w0.z, fmaf(a1, w1.z, bb.z)), 0.0f);
    v.w = fmaxf(fmaf(a0, w0.w, fmaf(a1, w1.w, bb.w)), 0.0f);
    uint32_t hi01 = pack_bf16x2(v.x, v.y);
    uint32_t hi23 = pack_bf16x2(v.z, v.w);
    float hx = __uint_as_float(hi01 << 16);
    float hy = __uint_as_float(hi01 & 0xFFFF0000u);
    float hz = __uint_as_float(hi23 << 16);
    float hw = __uint_as_float(hi23 & 0xFFFF0000u);
    uint32_t lo01 = pack_bf16x2(v.x - hx, v.y - hy);
    uint32_t lo23 = pack_bf16x2(v.z - hz, v.w - hw);
    size_t idx = (size_t)node * HDIM + c;
    *(uint2*)&g_h1_hi[idx] = make_uint2(hi01, hi23);
    *(uint2*)&g_h1_lo[idx] = make_uint2(lo01, lo23);
}

// --------------------- Aggregation for 128-dim layers -----------------------
// warp per node, lane owns 4 halves (8B); fp32 accumulate; bf16 hi/lo out.
__global__ void agg_kernel(int n) {
    int gt = blockIdx.x * blockDim.x + threadIdx.x;
    int node = gt >> 5, lane = gt & 31;
    if (node >= n) return;
    const uint2* hp = (const uint2*)g_h;   // 4 halves per uint2, 32 per row
    float4 acc = h4_to_f4(hp[(size_t)node * 32 + lane]);
    int o = g_off[node], d = g_deg[node];
    int e = 0;
    int d4 = d & ~3;
    for (; e < d4; e += 4) {
        int s0 = g_csr[o + e];
        int s1 = g_csr[o + e + 1];
        int s2 = g_csr[o + e + 2];
        int s3 = g_csr[o + e + 3];
        float4 v0 = h4_to_f4(hp[(size_t)s0 * 32 + lane]);
        float4 v1 = h4_to_f4(hp[(size_t)s1 * 32 + lane]);
        float4 v2 = h4_to_f4(hp[(size_t)s2 * 32 + lane]);
        float4 v3 = h4_to_f4(hp[(size_t)s3 * 32 + lane]);
        acc.x += v0.x + v1.x + v2.x + v3.x;
        acc.y += v0.y + v1.y + v2.y + v3.y;
        acc.z += v0.z + v1.z + v2.z + v3.z;
        acc.w += v0.w + v1.w + v2.w + v3.w;
    }
    for (; e < d; e++) {
        int s = g_csr[o + e];
        float4 v = h4_to_f4(hp[(size_t)s * 32 + lane]);
        acc.x += v.x; acc.y += v.y; acc.z += v.z; acc.w += v.w;
    }
    uint32_t hi01 = pack_bf16x2(acc.x, acc.y);
    uint32_t hi23 = pack_bf16x2(acc.z, acc.w);
    float hx = __uint_as_float(hi01 << 16);
    float hy = __uint_as_float(hi01 & 0xFFFF0000u);
    float hz = __uint_as_float(hi23 << 16);
    float hw = __uint_as_float(hi23 & 0xFFFF0000u);
    uint32_t lo01 = pack_bf16x2(acc.x - hx, acc.y - hy);
    uint32_t lo23 = pack_bf16x2(acc.z - hz, acc.w - hw);
    size_t idx = (size_t)node * HDIM + lane * 4;
    *(uint2*)&g_hpre_hi[idx] = make_uint2(hi01, hi23);
    *(uint2*)&g_hpre_lo[idx] = make_uint2(lo01, lo23);
}

// ------------------- Fused MLP GEMM (and single-GEMM mode) ------------------
#define PITCH 272
#define PLANE 34816
#define A_HI 2048
#define WA_HI 71680
#define WB_HI 141312
#define GEMM_SMEM_BYTES 210944

__device__ __forceinline__ void mma_block(uint32_t a0, uint32_t a1, uint32_t bw,
                                          float acc[2][8][4]) {
#pragma unroll
    for (int ks = 0; ks < 8; ks++) {
        uint32_t ko = ks * 32;
        uint32_t ah[2][4], al[2][4];
        ldsm_x4(ah[0], a0 + ko);
        ldsm_x4(ah[1], a1 + ko);
        ldsm_x4(al[0], a0 + PLANE + ko);
        ldsm_x4(al[1], a1 + PLANE + ko);
        uint32_t bh[8][2], bl[8][2];
#pragma unroll
        for (int q = 0; q < 4; q++) {
            ldsm_x4(&bh[2 * q][0], bw + q * 16 * PITCH + ko);
            ldsm_x4(&bl[2 * q][0], bw + PLANE + q * 16 * PITCH + ko);
        }
#pragma unroll
        for (int ti = 0; ti < 2; ti++) {
#pragma unroll
            for (int tj = 0; tj < 8; tj++) {
                mma_bf16(acc[ti][tj], ah[ti], bh[tj]);
                mma_bf16(acc[ti][tj], ah[ti], bl[tj]);
                mma_bf16(acc[ti][tj], al[ti], bh[tj]);
            }
        }
    }
}

__global__ void __launch_bounds__(256)
gemm_mlp(const unsigned short* __restrict__ Ahi,
         const unsigned short* __restrict__ Alo,
         const unsigned short* __restrict__ W1p,   // nullptr => single GEMM
         const unsigned short* __restrict__ W2p,
         const float* __restrict__ b1, const float* __restrict__ b2,
         const float* __restrict__ gamma, const float* __restrict__ beta,
         const float* __restrict__ mean, const float* __restrict__ var,
         __half* __restrict__ C, int n) {
    extern __shared__ __align__(16) char smem[];
    uint32_t sb = smem_to_u32(smem);
    int tid = threadIdx.x;
    int wid = tid >> 5;
    int lane = tid & 31;
    int row0 = blockIdx.x * 128;
    bool fused = (W1p != nullptr);

    // group 0: A planes + first W
#pragma unroll
    for (int it = 0; it < 16; it++) {
        int idx = it * 256 + tid;
        int plane = idx >> 11;
        int r2 = idx & 2047;
        int row = r2 >> 4, cu = r2 & 15;
        const unsigned short* s = (plane ? Alo : Ahi) +
                                  ((size_t)(row0 + row) * 128 + cu * 8);
        cp16(sb + A_HI + plane * PLANE + row * PITCH + cu * 16, s);
    }
    const unsigned short* Wa = fused ? W1p : W2p;
#pragma unroll
    for (int it = 0; it < 16; it++) {
        int idx = it * 256 + tid;
        int plane = idx >> 11;
        int r2 = idx & 2047;
        int row = r2 >> 4, cu = r2 & 15;
        cp16(sb + WA_HI + plane * PLANE + row * PITCH + cu * 16,
             Wa + plane * 16384 + row * 128 + cu * 8);
    }
    CP_COMMIT();
    if (fused) {
#pragma unroll
        for (int it = 0; it < 16; it++) {
            int idx = it * 256 + tid;
            int plane = idx >> 11;
            int r2 = idx & 2047;
            int row = r2 >> 4, cu = r2 & 15;
            cp16(sb + WB_HI + plane * PLANE + row * PITCH + cu * 16,
                 W2p + plane * 16384 + row * 128 + cu * 8);
        }
        CP_COMMIT();
    }

    float* sm_b1 = (float*)(smem + 0);
    float* sm_b2 = (float*)(smem + 512);
    float* sm_sc = (float*)(smem + 1024);
    float* sm_sh = (float*)(smem + 1536);
    if (tid < 128) {
        sm_b1[tid] = fused ? b1[tid] : 0.0f;
        sm_b2[tid] = b2[tid];
        float scv = 1.0f, shv = 0.0f;
        if (gamma != nullptr) {
            scv = gamma[tid] * rsqrtf(var[tid] + 1e-5f);
            shv = beta[tid] - mean[tid] * scv;
        }
        sm_sc[tid] = scv; sm_sh[tid] = shv;
    }
    if (fused) { CP_WAIT1(); } else { CP_WAIT0(); }
    __syncthreads();

    int m0 = (wid & 3) * 32;
    int n0 = (wid >> 2) * 64;
    int lr = lane & 7;
    int mi = lane >> 3;
    uint32_t a0_addr = sb + A_HI + (uint32_t)(m0 + (mi & 1) * 8 + lr) * PITCH + (mi >> 1) * 16;
    uint32_t a1_addr = a0_addr + 16 * PITCH;
    uint32_t ba_addr = sb + WA_HI + (uint32_t)(n0 + (mi >> 1) * 8 + lr) * PITCH + (mi & 1) * 16;

    float acc[2][8][4];
#pragma unroll
    for (int ti = 0; ti < 2; ti++)
#pragma unroll
        for (int tj = 0; tj < 8; tj++)
#pragma unroll
            for (int q = 0; q < 4; q++) acc[ti][tj][q] = 0.0f;

    mma_block(a0_addr, a1_addr, ba_addr, acc);

    int rb = m0 + (lane >> 2);
    int cb = n0 + (lane & 3) * 2;

    if (fused) {
        __syncthreads();
        CP_WAIT0();
#pragma unroll
        for (int tj = 0; tj < 8; tj++) {
            int col = cb + tj * 8;
            float bb0 = sm_b1[col], bb1 = sm_b1[col + 1];
#pragma unroll
            for (int ti = 0; ti < 2; ti++) {
                int r = rb + ti * 16;
                float v0 = fmaxf(acc[ti][tj][0] + bb0, 0.0f);
                float v1 = fmaxf(acc[ti][tj][1] + bb1, 0.0f);
                uint32_t hi = pack_bf16x2(v0, v1);
                float h0 = __uint_as_float(hi << 16);
                float h1 = __uint_as_float(hi & 0xFFFF0000u);
                uint32_t lo = pack_bf16x2(v0 - h0, v1 - h1);
                *(uint32_t*)(smem + A_HI + r * PITCH + col * 2) = hi;
                *(uint32_t*)(smem + A_HI + PLANE + r * PITCH + col * 2) = lo;
                float w0 = fmaxf(acc[ti][tj][2] + bb0, 0.0f);
                float w1 = fmaxf(acc[ti][tj][3] + bb1, 0.0f);
                uint32_t hi2 = pack_bf16x2(w0, w1);
                float g0 = __uint_as_float(hi2 << 16);
                float g1 = __uint_as_float(hi2 & 0xFFFF0000u);
                uint32_t lo2 = pack_bf16x2(w0 - g0, w1 - g1);
                *(uint32_t*)(smem + A_HI + (r + 8) * PITCH + col * 2) = hi2;
                *(uint32_t*)(smem + A_HI + PLANE + (r + 8) * PITCH + col * 2) = lo2;
                acc[ti][tj][0] = 0.0f; acc[ti][tj][1] = 0.0f;
                acc[ti][tj][2] = 0.0f; acc[ti][tj][3] = 0.0f;
            }
        }
        __syncthreads();
        uint32_t bb_addr = sb + WB_HI + (uint32_t)(n0 + (mi >> 1) * 8 + lr) * PITCH + (mi & 1) * 16;
        mma_block(a0_addr, a1_addr, bb_addr, acc);
    }

    // final epilogue: bias2, relu, BN affine -> C (fp16)
    int rbase = row0 + rb;
#pragma unroll
    for (int tj = 0; tj < 8; tj++) {
        int col = cb + tj * 8;
        float b0 = sm_b2[col], b1v = sm_b2[col + 1];
        float s0 = sm_sc[col], s1 = sm_sc[col + 1];
        float h0 = sm_sh[col], h1 = sm_sh[col + 1];
#pragma unroll
        for (int ti = 0; ti < 2; ti++) {
            int r = rbase + ti * 16;
            if (r < n) {
                float vx = fmaxf(acc[ti][tj][0] + b0, 0.0f) * s0 + h0;
                float vy = fmaxf(acc[ti][tj][1] + b1v, 0.0f) * s1 + h1;
                *(__half2*)&C[(size_t)r * 128 + col] = __floats2half2_rn(vx, vy);
            }
            if (r + 8 < n) {
                float vx = fmaxf(acc[ti][tj][2] + b0, 0.0f) * s0 + h0;
                float vy = fmaxf(acc[ti][tj][3] + b1v, 0.0f) * s1 + h1;
                *(__half2*)&C[(size_t)(r + 8) * 128 + col] = __floats2half2_rn(vx, vy);
            }
        }
    }
}

// --------------------------- Fused pool + head ------------------------------
// batch sorted -> contiguous ranges. One block per graph: pool then MLP head.
__global__ void pool_head_kernel(const int* __restrict__ batch, int n,
                                 const float* __restrict__ lin1W,
                                 const float* __restrict__ lin1b,
                                 const float* __restrict__ lin2W,
                                 const float* __restrict__ lin2b,
                                 float* __restrict__ out) {
    int gid = blockIdx.x;
    int j = threadIdx.x;
    __shared__ int se[2];
    __shared__ float row[128];
    __shared__ float red[128];
    if (j < 2) {
        int target = gid + j;
        int lo = 0, hi = n;
        while (lo < hi) {
            int mid = (lo + hi) >> 1;
            if (batch[mid] < target) lo = mid + 1; else hi = mid;
        }
        se[j] = lo;
    }
    __syncthreads();
    float acc = 0.0f;
    int s = se[0], e = se[1];
    for (int r = s; r < e; r++) acc += __half2float(g_h[(size_t)r * HDIM + j]);
    row[j] = acc;
    __syncthreads();
    float a = lin1b[j];
#pragma unroll 8
    for (int k = 0; k < 128; k++) a = fmaf(row[k], lin1W[k * 128 + j], a);
    a = fmaxf(a, 0.0f);
    red[j] = a * lin2W[j];
    __syncthreads();
#pragma unroll
    for (int st = 64; st > 0; st >>= 1) {
        if (j < st) red[j] += red[j + st];
        __syncthreads();
    }
    if (j == 0) out[gid] = red[0] + lin2b[0];
}

// ------------------------------- Launch --------------------------------------

extern "C" void kernel_launch(void* const* d_in, const int* in_sizes, int n_in,
                              void* d_out, int out_size) {
    const float* x     = (const float*)d_in[0];
    const int*   ei    = (const int*)d_in[1];
    const int*   batch = (const int*)d_in[2];
    const float* c1W1 = (const float*)d_in[3];
    const float* c1b1 = (const float*)d_in[4];
    const float* c1W2 = (const float*)d_in[5];
    const float* c1b2 = (const float*)d_in[6];
    const float* c1gm = (const float*)d_in[7];
    const float* c1bt = (const float*)d_in[8];
    const float* c1mn = (const float*)d_in[9];
    const float* c1vr = (const float*)d_in[10];
    const float* cW1  = (const float*)d_in[11];
    const float* cb1  = (const float*)d_in[12];
    const float* cW2  = (const float*)d_in[13];
    const float* cb2  = (const float*)d_in[14];
    const float* cgm  = (const float*)d_in[15];
    const float* cbt  = (const float*)d_in[16];
    const float* cmn  = (const float*)d_in[17];
    const float* cvr  = (const float*)d_in[18];
    const float* l1W  = (const float*)d_in[19];
    const float* l1b  = (const float*)d_in[20];
    const float* l2W  = (const float*)d_in[21];
    const float* l2b  = (const float*)d_in[22];
    float* out = (float*)d_out;

    int n = in_sizes[0] / 2;
    int e = in_sizes[1] / 2;
    int nl = in_sizes[11] / (HDIM * HDIM);
    int g = out_size;

    const int* src = ei;
    const int* dst = ei + e;

    __half* p_h;
    unsigned short *p_wprep, *p_hpre_hi, *p_hpre_lo, *p_h1_hi, *p_h1_lo;
    cudaGetSymbolAddress((void**)&p_h, g_h);
    cudaGetSymbolAddress((void**)&p_wprep, g_wprep);
    cudaGetSymbolAddress((void**)&p_hpre_hi, g_hpre_hi);
    cudaGetSymbolAddress((void**)&p_hpre_lo, g_hpre_lo);
    cudaGetSymbolAddress((void**)&p_h1_hi, g_h1_hi);
    cudaGetSymbolAddress((void**)&p_h1_lo, g_h1_lo);

    cudaFuncSetAttribute(gemm_mlp, cudaFuncAttributeMaxDynamicSharedMemorySize,
                         GEMM_SMEM_BYTES);

    // CSR build + weight prep
    zero_kernel<<<(n + 255) / 256, 256>>>(n);
    hist_kernel<<<(e + 255) / 256, 256>>>(dst, e, n);
    scan_kernel<<<1, 1024>>>(n);
    fill_kernel<<<(e + 255) / 256, 256>>>(src, dst, e, n);
    wprep_kernel<<<(1 * 16384 + 255) / 256, 256>>>(c1W2, 0, 1);
    wprep_kernel<<<(nl * 16384 + 255) / 256, 256>>>(cW1, 1, nl);
    wprep_kernel<<<(nl * 16384 + 255) / 256, 256>>>(cW2, 1 + nl, nl);

    int gemm_blocks = (n + 127) / 128;
    int warp_grid = (n * 32 + 255) / 256;

    // Layer 0: fused agg(dim2)+MLP1 -> single GEMM(W2)+BN
    agg_mlp0_kernel<<<warp_grid, 256>>>(x, c1W1, c1b1, n);
    gemm_mlp<<<gemm_blocks, 256, GEMM_SMEM_BYTES>>>(
        p_h1_hi, p_h1_lo, nullptr, p_wprep, nullptr, c1b2,
        c1gm, c1bt, c1mn, c1vr, p_h, n);

    // Layers 1..nl: agg (fp16 gather) -> fused MLP (2 GEMMs) + BN
    for (int i = 0; i < nl; i++) {
        agg_kernel<<<warp_grid, 256>>>(n);
        gemm_mlp<<<gemm_blocks, 256, GEMM_SMEM_BYTES>>>(
            p_hpre_hi, p_hpre_lo,
            p_wprep + (size_t)(1 + i) * 32768,
            p_wprep + (size_t)(1 + nl + i) * 32768,
            cb1 + (size_t)i * HDIM, cb2 + (size_t)i * HDIM,
            cgm + (size_t)i * HDIM, cbt + (size_t)i * HDIM,
            cmn + (size_t)i * HDIM, cvr + (size_t)i * HDIM, p_h, n);
    }

    // Fused pool + head
    pool_head_kernel<<<g, 128>>>(batch, n, l1W, l1b, l2W, l2b, out);
}

// round 14
// speedup vs baseline: 1.4380x; 1.1569x over previous
#include <cuda_runtime.h>
#include <cuda_fp16.h>
#include <cstdint>

// ----------------------------------------------------------------------------
// GIN forward on GB300 (base sm_103 PTX): CSR gather aggregation over fp16
// node features + fused-MLP mma.sync fp16 GEMMs (A = fp16, W = fp16 hi+lo
// 2-term exact-product scheme). Power-of-2 dynamic-range scaling:
//   g_h stores h/16, g_hpre stores hpre/256, smem h1 stores h1/256.
// All scales exact (powers of 2); folded into epilogue constants.
// ----------------------------------------------------------------------------

#define NMAX 50048
#define EMAX 800000
#define HDIM 128
#define GMAX 512

#define H_SCALE_INV 0.0625f      // 1/16 : h storage scale
#define H_SCALE 16.0f
#define A_SCALE 256.0f           // hpre / h1 GEMM input scale
#define A_SCALE_INV 0.00390625f  // 1/256

__device__ __half g_h[(size_t)NMAX * HDIM];     // h/16 (fp16)
__device__ __half g_hpre[(size_t)NMAX * HDIM];  // hpre/256 (fp16)
__device__ __half g_h1[(size_t)NMAX * HDIM];    // layer0 mlp1 out (unscaled)
__device__ int   g_deg[NMAX];
__device__ int   g_off[NMAX];
__device__ int   g_cnt[NMAX];
__device__ int   g_csr[EMAX];
// 9 weight mats x (hi plane 16384 + lo plane 16384) fp16, transposed [n][k]
__device__ __half g_wprep[9 * 32768];

// ------------------------------ helpers -------------------------------------

__device__ __forceinline__ uint32_t smem_to_u32(const void* p) {
    uint32_t a;
    asm("{ .reg .u64 t; cvta.to.shared.u64 t, %1; cvt.u32.u64 %0, t; }"
        : "=r"(a) : "l"(p));
    return a;
}

__device__ __forceinline__ void ldsm_x4(uint32_t r[4], uint32_t addr) {
    asm volatile("ldmatrix.sync.aligned.m8n8.x4.shared.b16 {%0,%1,%2,%3}, [%4];"
                 : "=r"(r[0]), "=r"(r[1]), "=r"(r[2]), "=r"(r[3]) : "r"(addr));
}

__device__ __forceinline__ void mma_f16(float c[4], const uint32_t a[4],
                                        const uint32_t b[2]) {
    asm volatile(
        "mma.sync.aligned.m16n8k16.row.col.f32.f16.f16.f32 "
        "{%0,%1,%2,%3}, {%4,%5,%6,%7}, {%8,%9}, {%0,%1,%2,%3};"
        : "+f"(c[0]), "+f"(c[1]), "+f"(c[2]), "+f"(c[3])
        : "r"(a[0]), "r"(a[1]), "r"(a[2]), "r"(a[3]), "r"(b[0]), "r"(b[1]));
}

__device__ __forceinline__ void cp16(uint32_t dst, const void* src) {
    asm volatile("cp.async.cg.shared.global [%0], [%1], 16;"
                 :: "r"(dst), "l"(src) : "memory");
}
#define CP_COMMIT() asm volatile("cp.async.commit_group;" ::: "memory")
#define CP_WAIT0()  asm volatile("cp.async.wait_group 0;" ::: "memory")
#define CP_WAIT1()  asm volatile("cp.async.wait_group 1;" ::: "memory")

__device__ __forceinline__ float4 h4_to_f4(uint2 r) {
    __half2 p0 = *reinterpret_cast<__half2*>(&r.x);
    __half2 p1 = *reinterpret_cast<__half2*>(&r.y);
    float2 f0 = __half22float2(p0);
    float2 f1 = __half22float2(p1);
    return make_float4(f0.x, f0.y, f1.x, f1.y);
}

__device__ __forceinline__ uint2 f4_to_h4(float4 v) {
    __half2 p0 = __floats2half2_rn(v.x, v.y);
    __half2 p1 = __floats2half2_rn(v.z, v.w);
    uint2 r;
    r.x = *reinterpret_cast<uint32_t*>(&p0);
    r.y = *reinterpret_cast<uint32_t*>(&p1);
    return r;
}

// ----------------------- Weight prep (fp16 hi/lo, [n][k]) -------------------

__global__ void wprep_kernel(const float* __restrict__ c1W2,
                             const float* __restrict__ cW1,
                             const float* __restrict__ cW2, int nl) {
    int i = blockIdx.x * blockDim.x + threadIdx.x;
    int total = (1 + 2 * nl) * 16384;
    if (i >= total) return;
    int m = i >> 14;
    int r = i & 16383;
    int k = r >> 7;
    int nn = r & 127;
    const float* src;
    if (m == 0) src = c1W2;
    else if (m <= nl) src = cW1 + (size_t)(m - 1) * 16384;
    else src = cW2 + (size_t)(m - 1 - nl) * 16384;
    float v = src[r];                 // [k][nn]
    __half hb = __float2half_rn(v);
    __half lb = __float2half_rn(v - __half2float(hb));
    int base = m * 32768;
    g_wprep[base + nn * 128 + k] = hb;
    g_wprep[base + 16384 + nn * 128 + k] = lb;
}

// --------------------------- CSR construction -------------------------------

__global__ void hist_kernel(const int* __restrict__ dst, int e, int n) {
    int i = blockIdx.x * blockDim.x + threadIdx.x;
    if (i < e) {
        int d = dst[i];
        if (d >= 0 && d < n) atomicAdd(&g_deg[d], 1);
    }
}

__global__ void scan_kernel(int n) {
    __shared__ int sums[1024];
    int t = threadIdx.x;
    int chunk = (n + 1023) >> 10;
    int start = t * chunk;
    int end = start + chunk; if (end > n) end = n;
    int s = 0;
    for (int i = start; i < end; i++) s += g_deg[i];
    sums[t] = s;
    __syncthreads();
    for (int d = 1; d < 1024; d <<= 1) {
        int v = (t >= d) ? sums[t - d] : 0;
        __syncthreads();
        sums[t] += v;
        __syncthreads();
    }
    int run = (t == 0) ? 0 : sums[t - 1];
    for (int i = start; i < end; i++) { g_off[i] = run; run += g_deg[i]; }
}

__global__ void fill_kernel(const int* __restrict__ src,
                            const int* __restrict__ dst, int e, int n) {
    int i = blockIdx.x * blockDim.x + threadIdx.x;
    if (i < e) {
        int d = dst[i];
        int s = src[i];
        if (d >= 0 && d < n && s >= 0 && s < n) {
            int p = g_off[d] + atomicAdd(&g_cnt[d], 1);
            g_csr[p] = s;
        }
    }
}

// -------------- Layer 0: fused agg(dim2) + MLP1 (warp per node) -------------

__global__ void agg_mlp0_kernel(const float* __restrict__ x,
                                const float* __restrict__ W1,
                                const float* __restrict__ b1, int n) {
    int gt = blockIdx.x * blockDim.x + threadIdx.x;
    int node = gt >> 5, lane = gt & 31;
    if (node >= n) return;
    int o = g_off[node], d = g_deg[node];
    float a0 = 0.0f, a1 = 0.0f;
    for (int e = lane; e < d; e += 32) {
        int s = g_csr[o + e];
        float2 v = *(const float2*)&x[s * 2];
        a0 += v.x; a1 += v.y;
    }
#pragma unroll
    for (int m = 16; m > 0; m >>= 1) {
        a0 += __shfl_xor_sync(0xFFFFFFFFu, a0, m);
        a1 += __shfl_xor_sync(0xFFFFFFFFu, a1, m);
    }
    float2 self = *(const float2*)&x[node * 2];
    a0 += self.x; a1 += self.y;

    int c = lane * 4;
    float4 w0 = *(const float4*)&W1[c];
    float4 w1 = *(const float4*)&W1[HDIM + c];
    float4 bb = *(const float4*)&b1[c];
    float4 v;
    v.x = fmaxf(fmaf(a0, w0.x, fmaf(a1, w1.x, bb.x)), 0.0f);
    v.y = fmaxf(fmaf(a0, w0.y, fmaf(a1, w1.y, bb.y)), 0.0f);
    v.z = fmaxf(fmaf(a0, w0.z, fmaf(a1, w1.z, bb.z)), 0.0f);
    v.w = fmaxf(fmaf(a0, w0.w, fmaf(a1, w1.w, bb.w)), 0.0f);
    *(uint2*)&g_h1[(size_t)node * HDIM + c] = f4_to_h4(v);
}

// --------------------- Aggregation for 128-dim layers -----------------------
// g_h holds h/16; fp32 acc = hpre/16; store acc/16 = hpre/256 (fp16).
__global__ void agg_kernel(int n) {
    int gt = blockIdx.x * blockDim.x + threadIdx.x;
    int node = gt >> 5, lane = gt & 31;
    if (node >= n) return;
    const uint2* hp = (const uint2*)g_h;
    float4 acc = h4_to_f4(hp[(size_t)node * 32 + lane]);
    int o = g_off[node], d = g_deg[node];
    int e = 0;
    int d4 = d & ~3;
    for (; e < d4; e += 4) {
        int s0 = g_csr[o + e];
        int s1 = g_csr[o + e + 1];
        int s2 = g_csr[o + e + 2];
        int s3 = g_csr[o + e + 3];
        float4 v0 = h4_to_f4(hp[(size_t)s0 * 32 + lane]);
        float4 v1 = h4_to_f4(hp[(size_t)s1 * 32 + lane]);
        float4 v2 = h4_to_f4(hp[(size_t)s2 * 32 + lane]);
        float4 v3 = h4_to_f4(hp[(size_t)s3 * 32 + lane]);
        acc.x += v0.x + v1.x + v2.x + v3.x;
        acc.y += v0.y + v1.y + v2.y + v3.y;
        acc.z += v0.z + v1.z + v2.z + v3.z;
        acc.w += v0.w + v1.w + v2.w + v3.w;
    }
    for (; e < d; e++) {
        int s = g_csr[o + e];
        float4 v = h4_to_f4(hp[(size_t)s * 32 + lane]);
        acc.x += v.x; acc.y += v.y; acc.z += v.z; acc.w += v.w;
    }
    acc.x *= H_SCALE_INV; acc.y *= H_SCALE_INV;
    acc.z *= H_SCALE_INV; acc.w *= H_SCALE_INV;
    *(uint2*)&g_hpre[(size_t)node * HDIM + lane * 4] = f4_to_h4(acc);
}

// ------------------- Fused MLP GEMM (and single-GEMM mode) ------------------
// A: single fp16 plane (pre-scaled by 1/ascale). W: fp16 hi+lo planes.
#define PITCH 272
#define PLANE 34816
#define A_OFF 2048
#define WA_OFF 36864
#define WB_OFF 106496
#define GEMM_SMEM_BYTES 176128

__device__ __forceinline__ void mma_block(uint32_t a0, uint32_t a1, uint32_t bw,
                                          float acc[2][8][4]) {
#pragma unroll
    for (int ks = 0; ks < 8; ks++) {
        uint32_t ko = ks * 32;
        uint32_t a[2][4];
        ldsm_x4(a[0], a0 + ko);
        ldsm_x4(a[1], a1 + ko);
        uint32_t bh[8][2], bl[8][2];
#pragma unroll
        for (int q = 0; q < 4; q++) {
            ldsm_x4(&bh[2 * q][0], bw + q * 16 * PITCH + ko);
            ldsm_x4(&bl[2 * q][0], bw + PLANE + q * 16 * PITCH + ko);
        }
#pragma unroll
        for (int ti = 0; ti < 2; ti++) {
#pragma unroll
            for (int tj = 0; tj < 8; tj++) {
                mma_f16(acc[ti][tj], a[ti], bh[tj]);
                mma_f16(acc[ti][tj], a[ti], bl[tj]);
            }
        }
    }
}

__global__ void __launch_bounds__(256)
gemm_mlp(const __half* __restrict__ Aa,
         const __half* __restrict__ W1p,   // nullptr => single GEMM
         const __half* __restrict__ W2p,
         const float* __restrict__ b1, const float* __restrict__ b2,
         const float* __restrict__ gamma, const float* __restrict__ beta,
         const float* __restrict__ mean, const float* __restrict__ var,
         __half* __restrict__ C, int n, float ascale) {
    extern __shared__ __align__(16) char smem[];
    uint32_t sb = smem_to_u32(smem);
    int tid = threadIdx.x;
    int wid = tid >> 5;
    int lane = tid & 31;
    int row0 = blockIdx.x * 128;
    bool fused = (W1p != nullptr);

    // group 0: A plane + first W
#pragma unroll
    for (int it = 0; it < 8; it++) {
        int idx = it * 256 + tid;            // 0..2047
        int row = idx >> 4, cu = idx & 15;
        cp16(sb + A_OFF + row * PITCH + cu * 16,
             Aa + ((size_t)(row0 + row) * 128 + cu * 8));
    }
    const __half* Wa = fused ? W1p : W2p;
#pragma unroll
    for (int it = 0; it < 16; it++) {
        int idx = it * 256 + tid;            // 0..4095
        int plane = idx >> 11;
        int r2 = idx & 2047;
        int row = r2 >> 4, cu = r2 & 15;
        cp16(sb + WA_OFF + plane * PLANE + row * PITCH + cu * 16,
             Wa + plane * 16384 + row * 128 + cu * 8);
    }
    CP_COMMIT();
    if (fused) {
#pragma unroll
        for (int it = 0; it < 16; it++) {
            int idx = it * 256 + tid;
            int plane = idx >> 11;
            int r2 = idx & 2047;
            int row = r2 >> 4, cu = r2 & 15;
            cp16(sb + WB_OFF + plane * PLANE + row * PITCH + cu * 16,
                 W2p + plane * 16384 + row * 128 + cu * 8);
        }
        CP_COMMIT();
    }

    float* sm_b1 = (float*)(smem + 0);     // b1 / ascale (mid relu, pre-rescale)
    float* sm_b2 = (float*)(smem + 512);
    float* sm_sc = (float*)(smem + 1024);  // BN scale * 1/16 (h storage scale)
    float* sm_sh = (float*)(smem + 1536);
    if (tid < 128) {
        sm_b1[tid] = fused ? b1[tid] * A_SCALE_INV : 0.0f;
        sm_b2[tid] = b2[tid];
        float scv = 1.0f, shv = 0.0f;
        if (gamma != nullptr) {
            scv = gamma[tid] * rsqrtf(var[tid] + 1e-5f);
            shv = beta[tid] - mean[tid] * scv;
        }
        sm_sc[tid] = scv * H_SCALE_INV;
        sm_sh[tid] = shv * H_SCALE_INV;
    }
    if (fused) { CP_WAIT1(); } else { CP_WAIT0(); }
    __syncthreads();

    int m0 = (wid & 3) * 32;
    int n0 = (wid >> 2) * 64;
    int lr = lane & 7;
    int mi = lane >> 3;
    uint32_t a0_addr = sb + A_OFF + (uint32_t)(m0 + (mi & 1) * 8 + lr) * PITCH + (mi >> 1) * 16;
    uint32_t a1_addr = a0_addr + 16 * PITCH;
    uint32_t ba_addr = sb + WA_OFF + (uint32_t)(n0 + (mi >> 1) * 8 + lr) * PITCH + (mi & 1) * 16;

    float acc[2][8][4];
#pragma unroll
    for (int ti = 0; ti < 2; ti++)
#pragma unroll
        for (int tj = 0; tj < 8; tj++)
#pragma unroll
            for (int q = 0; q < 4; q++) acc[ti][tj][q] = 0.0f;

    mma_block(a0_addr, a1_addr, ba_addr, acc);

    int rb = m0 + (lane >> 2);
    int cb = n0 + (lane & 3) * 2;

    if (fused) {
        __syncthreads();
        CP_WAIT0();
        // h1/256 = relu(acc + b1/256)  (acc = (hpre/256)@W1) -> fp16 A plane
#pragma unroll
        for (int tj = 0; tj < 8; tj++) {
            int col = cb + tj * 8;
            float bb0 = sm_b1[col], bb1 = sm_b1[col + 1];
#pragma unroll
            for (int ti = 0; ti < 2; ti++) {
                int r = rb + ti * 16;
                __half2 p0 = __floats2half2_rn(fmaxf(acc[ti][tj][0] + bb0, 0.0f),
                                               fmaxf(acc[ti][tj][1] + bb1, 0.0f));
                *(uint32_t*)(smem + A_OFF + r * PITCH + col * 2) =
                    *reinterpret_cast<uint32_t*>(&p0);
                __half2 p1 = __floats2half2_rn(fmaxf(acc[ti][tj][2] + bb0, 0.0f),
                                               fmaxf(acc[ti][tj][3] + bb1, 0.0f));
                *(uint32_t*)(smem + A_OFF + (r + 8) * PITCH + col * 2) =
                    *reinterpret_cast<uint32_t*>(&p1);
                acc[ti][tj][0] = 0.0f; acc[ti][tj][1] = 0.0f;
                acc[ti][tj][2] = 0.0f; acc[ti][tj][3] = 0.0f;
            }
        }
        __syncthreads();
        uint32_t bb_addr = sb + WB_OFF + (uint32_t)(n0 + (mi >> 1) * 8 + lr) * PITCH + (mi & 1) * 16;
        mma_block(a0_addr, a1_addr, bb_addr, acc);
    }

    // final epilogue: h/16 = (relu(acc*ascale + b2)*sc + sh)/16 -> C (fp16)
    int rbase = row0 + rb;
#pragma unroll
    for (int tj = 0; tj < 8; tj++) {
        int col = cb + tj * 8;
        float b0 = sm_b2[col], b1v = sm_b2[col + 1];
        float s0 = sm_sc[col], s1 = sm_sc[col + 1];
        float h0 = sm_sh[col], h1 = sm_sh[col + 1];
#pragma unroll
        for (int ti = 0; ti < 2; ti++) {
            int r = rbase + ti * 16;
            if (r < n) {
                float vx = fmaxf(fmaf(acc[ti][tj][0], ascale, b0), 0.0f) * s0 + h0;
                float vy = fmaxf(fmaf(acc[ti][tj][1], ascale, b1v), 0.0f) * s1 + h1;
                *(__half2*)&C[(size_t)r * 128 + col] = __floats2half2_rn(vx, vy);
            }
            if (r + 8 < n) {
                float vx = fmaxf(fmaf(acc[ti][tj][2], ascale, b0), 0.0f) * s0 + h0;
                float vy = fmaxf(fmaf(acc[ti][tj][3], ascale, b1v), 0.0f) * s1 + h1;
                *(__half2*)&C[(size_t)(r + 8) * 128 + col] = __floats2half2_rn(vx, vy);
            }
        }
    }
}

// --------------------------- Fused pool + head ------------------------------
// g_h holds h/16 -> multiply pooled row by 16.
__global__ void pool_head_kernel(const int* __restrict__ batch, int n,
                                 const float* __restrict__ lin1W,
                                 const float* __restrict__ lin1b,
                                 const float* __restrict__ lin2W,
                                 const float* __restrict__ lin2b,
                                 float* __restrict__ out) {
    int gid = blockIdx.x;
    int j = threadIdx.x;
    __shared__ int se[2];
    __shared__ float row[128];
    __shared__ float red[128];
    if (j < 2) {
        int target = gid + j;
        int lo = 0, hi = n;
        while (lo < hi) {
            int mid = (lo + hi) >> 1;
            if (batch[mid] < target) lo = mid + 1; else hi = mid;
        }
        se[j] = lo;
    }
    __syncthreads();
    float acc = 0.0f;
    int s = se[0], e = se[1];
    for (int r = s; r < e; r++) acc += __half2float(g_h[(size_t)r * HDIM + j]);
    row[j] = acc * H_SCALE;
    __syncthreads();
    float a = lin1b[j];
#pragma unroll 8
    for (int k = 0; k < 128; k++) a = fmaf(row[k], lin1W[k * 128 + j], a);
    a = fmaxf(a, 0.0f);
    red[j] = a * lin2W[j];
    __syncthreads();
#pragma unroll
    for (int st = 64; st > 0; st >>= 1) {
        if (j < st) red[j] += red[j + st];
        __syncthreads();
    }
    if (j == 0) out[gid] = red[0] + lin2b[0];
}

// ------------------------------- Launch --------------------------------------

extern "C" void kernel_launch(void* const* d_in, const int* in_sizes, int n_in,
                              void* d_out, int out_size) {
    const float* x     = (const float*)d_in[0];
    const int*   ei    = (const int*)d_in[1];
    const int*   batch = (const int*)d_in[2];
    const float* c1W1 = (const float*)d_in[3];
    const float* c1b1 = (const float*)d_in[4];
    const float* c1W2 = (const float*)d_in[5];
    const float* c1b2 = (const float*)d_in[6];
    const float* c1gm = (const float*)d_in[7];
    const float* c1bt = (const float*)d_in[8];
    const float* c1mn = (const float*)d_in[9];
    const float* c1vr = (const float*)d_in[10];
    const float* cW1  = (const float*)d_in[11];
    const float* cb1  = (const float*)d_in[12];
    const float* cW2  = (const float*)d_in[13];
    const float* cb2  = (const float*)d_in[14];
    const float* cgm  = (const float*)d_in[15];
    const float* cbt  = (const float*)d_in[16];
    const float* cmn  = (const float*)d_in[17];
    const float* cvr  = (const float*)d_in[18];
    const float* l1W  = (const float*)d_in[19];
    const float* l1b  = (const float*)d_in[20];
    const float* l2W  = (const float*)d_in[21];
    const float* l2b  = (const float*)d_in[22];
    float* out = (float*)d_out;

    int n = in_sizes[0] / 2;
    int e = in_sizes[1] / 2;
    int nl = in_sizes[11] / (HDIM * HDIM);
    int g = out_size;

    const int* src = ei;
    const int* dst = ei + e;

    __half *p_h, *p_hpre, *p_h1, *p_wprep;
    int *p_deg, *p_cnt;
    cudaGetSymbolAddress((void**)&p_h, g_h);
    cudaGetSymbolAddress((void**)&p_hpre, g_hpre);
    cudaGetSymbolAddress((void**)&p_h1, g_h1);
    cudaGetSymbolAddress((void**)&p_wprep, g_wprep);
    cudaGetSymbolAddress((void**)&p_deg, g_deg);
    cudaGetSymbolAddress((void**)&p_cnt, g_cnt);

    cudaFuncSetAttribute(gemm_mlp, cudaFuncAttributeMaxDynamicSharedMemorySize,
                         GEMM_SMEM_BYTES);

    cudaMemsetAsync(p_deg, 0, (size_t)n * sizeof(int));
    cudaMemsetAsync(p_cnt, 0, (size_t)n * sizeof(int));

    int wtot = (1 + 2 * nl) * 16384;
    wprep_kernel<<<(wtot + 255) / 256, 256>>>(c1W2, cW1, cW2, nl);
    hist_kernel<<<(e + 255) / 256, 256>>>(dst, e, n);
    scan_kernel<<<1, 1024>>>(n);
    fill_kernel<<<(e + 255) / 256, 256>>>(src, dst, e, n);

    int gemm_blocks = (n + 127) / 128;
    int warp_grid = (n * 32 + 255) / 256;

    // Layer 0: fused agg(dim2)+MLP1 -> single GEMM(W2)+BN (A unscaled)
    agg_mlp0_kernel<<<warp_grid, 256>>>(x, c1W1, c1b1, n);
    gemm_mlp<<<gemm_blocks, 256, GEMM_SMEM_BYTES>>>(
        p_h1, nullptr, p_wprep, nullptr, c1b2,
        c1gm, c1bt, c1mn, c1vr, p_h, n, 1.0f);

    // Layers 1..nl: agg (fp16, hpre/256) -> fused MLP (ascale=256) + BN
    for (int i = 0; i < nl; i++) {
        agg_kernel<<<warp_grid, 256>>>(n);
        gemm_mlp<<<gemm_blocks, 256, GEMM_SMEM_BYTES>>>(
            p_hpre,
            p_wprep + (size_t)(1 + i) * 32768,
            p_wprep + (size_t)(1 + nl + i) * 32768,
            cb1 + (size_t)i * HDIM, cb2 + (size_t)i * HDIM,
            cgm + (size_t)i * HDIM, cbt + (size_t)i * HDIM,
            cmn + (size_t)i * HDIM, cvr + (size_t)i * HDIM, p_h, n, A_SCALE);
    }

    // Fused pool + head
    pool_head_kernel<<<g, 128>>>(batch, n, l1W, l1b, l2W, l2b, out);
}